// round 1
// baseline (speedup 1.0000x reference)
#include <cuda_runtime.h>
#include <math.h>

#define B_    256
#define T_    64
#define NAG   10
#define NFEAT 4
#define XDIM  44
#define XPERM 40
#define XSTAT 10
#define HIDD  128
#define XEMBD 32
#define NHIDD 8
#define E_    90
#define GEMBD 720
#define UD    768            // padded from 763
#define ND    640            // 128 (a) + 128 (o) + 384 (gi)
#define M_    (B_ * T_)      // 16384
#define KD    768
#define OUTW  130            // a_out, y_out, hs[128]

// ---- scratch (device globals; no runtime allocation) ----
__device__ __align__(16) float g_U[M_ * UD];       // 48 MB
__device__ __align__(16) float g_Wt[KD * ND];      // 1.9 MB, layout [k][n]
__device__ __align__(16) float g_bias[ND];
__device__ __align__(16) float g_C[M_ * ND];       // 40 MB
__device__ __align__(16) float g_demo[B_ * XSTAT];

// ------------------------------------------------------------------
// demo = x_demo @ W_stat.T + b_stat
// ------------------------------------------------------------------
__global__ void demo_kernel(const float* __restrict__ xd,
                            const float* __restrict__ Ws,
                            const float* __restrict__ bs) {
    int i = blockIdx.x * blockDim.x + threadIdx.x;
    if (i >= B_ * XSTAT) return;
    int b = i / XSTAT, o = i % XSTAT;
    float acc = bs[o];
#pragma unroll
    for (int k = 0; k < XSTAT; k++) acc += xd[b * XSTAT + k] * Ws[o * XSTAT + k];
    g_demo[i] = acc;
}

// ------------------------------------------------------------------
// Per-(b,t): message passing (h1 -> edges -> h2 -> gemb), xemb, assemble U row
// ------------------------------------------------------------------
__device__ __forceinline__ float elu1(float v) { return v > 0.f ? v : expm1f(v); }

__global__ void feat_kernel(const float* __restrict__ x,
                            const float* __restrict__ ft,
                            const float* __restrict__ Wm1a, const float* __restrict__ bm1a,
                            const float* __restrict__ Wm1b, const float* __restrict__ bm1b,
                            const float* __restrict__ Wm2a, const float* __restrict__ bm2a,
                            const float* __restrict__ Wm2b, const float* __restrict__ bm2b,
                            const float* __restrict__ Wx2,  const float* __restrict__ bx2) {
    int m = blockIdx.x;               // b*T + t
    int b = m / T_, t = m % T_;
    int tid = threadIdx.x;            // 128 threads

    __shared__ float s_x[XDIM];
    __shared__ float s_h1a[NAG * NHIDD];
    __shared__ float s_h1[NAG * NHIDD];
    __shared__ float s_h2a[E_ * NHIDD];

    const float* xr = x + ((size_t)b * (T_ + 1) + t) * XDIM;
    if (tid < XDIM) s_x[tid] = xr[tid];
    __syncthreads();

    if (tid < NAG * NHIDD) {
        int a = tid / NHIDD, o = tid % NHIDD;
        float acc = bm1a[o];
#pragma unroll
        for (int f = 0; f < NFEAT; f++) acc += s_x[a * NFEAT + f] * Wm1a[o * NFEAT + f];
        s_h1a[tid] = elu1(acc);
    }
    __syncthreads();
    if (tid < NAG * NHIDD) {
        int a = tid / NHIDD, o = tid % NHIDD;
        float acc = bm1b[o];
#pragma unroll
        for (int k = 0; k < NHIDD; k++) acc += s_h1a[a * NHIDD + k] * Wm1b[o * NHIDD + k];
        s_h1[tid] = elu1(acc);
    }
    __syncthreads();

    // edges: e = r*9 + jj ; send = jj < r ? jj : jj+1
    for (int i = tid; i < E_ * NHIDD; i += 128) {
        int e = i / NHIDD, o = i % NHIDD;
        int r = e / (NAG - 1), jj = e % (NAG - 1);
        int s = jj < r ? jj : jj + 1;
        float acc = bm2a[o];
#pragma unroll
        for (int k = 0; k < NHIDD; k++)
            acc += s_h1[r * NHIDD + k] * Wm2a[o * 16 + k]
                 + s_h1[s * NHIDD + k] * Wm2a[o * 16 + 8 + k];
        s_h2a[i] = elu1(acc);
    }
    __syncthreads();

    float* u = g_U + (size_t)m * UD;
    for (int i = tid; i < E_ * NHIDD; i += 128) {
        int e = i / NHIDD, o = i % NHIDD;
        float acc = bm2b[o];
#pragma unroll
        for (int k = 0; k < NHIDD; k++) acc += s_h2a[e * NHIDD + k] * Wm2b[o * NHIDD + k];
        u[43 + i] = elu1(acc);
    }

    if (tid < XEMBD) {
        float acc = bx2[tid];
#pragma unroll
        for (int f = 0; f < XDIM - XPERM; f++)
            acc += s_x[XPERM + f] * Wx2[tid * (XDIM - XPERM) + f];
        u[tid] = acc;
    }
    if (tid >= XEMBD && tid < XEMBD + XSTAT)
        u[tid] = g_demo[b * XSTAT + (tid - XEMBD)];
    if (tid == 42) u[42] = ft[(size_t)b * (T_ + 1) + t];
    if (tid >= 43 && tid < 48) u[763 + (tid - 43)] = 0.f;  // pad
}

// ------------------------------------------------------------------
// Repack W_a1 / W_o1 / W_ih into g_Wt[k][n] (K-major) + fused bias
// ------------------------------------------------------------------
__global__ void repack_kernel(const float* __restrict__ Wa1, const float* __restrict__ ba1,
                              const float* __restrict__ Wo1, const float* __restrict__ bo1,
                              const float* __restrict__ Wih, const float* __restrict__ bih) {
    int idx = blockIdx.x * blockDim.x + threadIdx.x;
    if (idx < ND)
        g_bias[idx] = idx < 128 ? ba1[idx] : (idx < 256 ? bo1[idx - 128] : bih[idx - 256]);

    int stride = gridDim.x * blockDim.x;
    for (int i = idx; i < KD * ND; i += stride) {
        int k = i / ND, n = i % ND;
        float v = 0.f;
        if (n < 128) {                                       // a: [demo(u32..41), gemb(u43..762)]
            if (k >= 32 && k < 42)       v = Wa1[n * 730 + (k - 32)];
            else if (k >= 43 && k < 763) v = Wa1[n * 730 + 10 + (k - 43)];
        } else if (n < 256) {                                // o: u[0..762] directly
            if (k < 763) v = Wo1[(n - 128) * 763 + k];
        } else {                                             // ih: [xemb(u0..31), treat(u42), gemb]
            int r = n - 256;
            if (k < 32)                  v = Wih[r * 753 + k];
            else if (k == 42)            v = Wih[r * 753 + 32];
            else if (k >= 43 && k < 763) v = Wih[r * 753 + 33 + (k - 43)];
        }
        g_Wt[i] = v;
    }
}

// ------------------------------------------------------------------
// SGEMM: C[16384 x 640] = U[16384 x 768] @ Wt (K-major) + bias
// 128x128 tile, BK=8, 256 threads, 8x8 micro-tile
// ------------------------------------------------------------------
#define BM 128
#define BN 128
#define BK 8

__global__ __launch_bounds__(256) void gemm_kernel() {
    __shared__ __align__(16) float As[BK][BM];
    __shared__ __align__(16) float Bs[BK][BN];

    int bx = blockIdx.x;   // 0..4   (N tiles)
    int by = blockIdx.y;   // 0..127 (M tiles)
    int tid = threadIdx.x;
    int tx = tid % 16, ty = tid / 16;

    const float* A = g_U + (size_t)by * BM * KD;

    int arow = tid >> 1;
    int ac4  = (tid & 1) * 4;
    int bk   = tid >> 5;
    int bn4  = (tid & 31) * 4;

    float acc[8][8];
#pragma unroll
    for (int i = 0; i < 8; i++)
#pragma unroll
        for (int j = 0; j < 8; j++) acc[i][j] = 0.f;

    for (int k0 = 0; k0 < KD; k0 += BK) {
        float4 av = *(const float4*)(A + (size_t)arow * KD + k0 + ac4);
        float4 bv = *(const float4*)(g_Wt + (size_t)(k0 + bk) * ND + bx * BN + bn4);
        __syncthreads();
        As[ac4 + 0][arow] = av.x;
        As[ac4 + 1][arow] = av.y;
        As[ac4 + 2][arow] = av.z;
        As[ac4 + 3][arow] = av.w;
        *(float4*)&Bs[bk][bn4] = bv;
        __syncthreads();
#pragma unroll
        for (int kk = 0; kk < BK; kk++) {
            float4 a0 = *(const float4*)&As[kk][ty * 8];
            float4 a1 = *(const float4*)&As[kk][ty * 8 + 4];
            float4 b0 = *(const float4*)&Bs[kk][tx * 8];
            float4 b1 = *(const float4*)&Bs[kk][tx * 8 + 4];
            float ra[8] = {a0.x, a0.y, a0.z, a0.w, a1.x, a1.y, a1.z, a1.w};
            float rb[8] = {b0.x, b0.y, b0.z, b0.w, b1.x, b1.y, b1.z, b1.w};
#pragma unroll
            for (int i = 0; i < 8; i++)
#pragma unroll
                for (int j = 0; j < 8; j++) acc[i][j] += ra[i] * rb[j];
        }
    }

    // epilogue with bias
    float bias[8];
#pragma unroll
    for (int j = 0; j < 8; j++) bias[j] = g_bias[bx * BN + tx * 8 + j];
#pragma unroll
    for (int i = 0; i < 8; i++) {
        size_t row = (size_t)by * BM + ty * 8 + i;
        float* cp = g_C + row * ND + bx * BN + tx * 8;
        float4 v0 = {acc[i][0] + bias[0], acc[i][1] + bias[1],
                     acc[i][2] + bias[2], acc[i][3] + bias[3]};
        float4 v1 = {acc[i][4] + bias[4], acc[i][5] + bias[5],
                     acc[i][6] + bias[6], acc[i][7] + bias[7]};
        *(float4*)cp = v0;
        *(float4*)(cp + 4) = v1;
    }
}

// ------------------------------------------------------------------
// heads: a_out = relu(a_hid) . W_a2 ; y_out = relu(o_hid) . W_o2
// one warp per row
// ------------------------------------------------------------------
__global__ void head_kernel(const float* __restrict__ Wa2,
                            const float* __restrict__ Wo2,
                            float* __restrict__ out) {
    int warp = (blockIdx.x * blockDim.x + threadIdx.x) >> 5;
    int lane = threadIdx.x & 31;
    if (warp >= M_) return;
    const float* c = g_C + (size_t)warp * ND;
    float a = 0.f, y = 0.f;
#pragma unroll
    for (int j = lane; j < 128; j += 32) {
        a += fmaxf(c[j], 0.f) * Wa2[j];
        y += fmaxf(c[128 + j], 0.f) * Wo2[j];
    }
#pragma unroll
    for (int s = 16; s; s >>= 1) {
        a += __shfl_down_sync(0xFFFFFFFFu, a, s);
        y += __shfl_down_sync(0xFFFFFFFFu, y, s);
    }
    if (lane == 0) {
        out[(size_t)warp * OUTW + 0] = a;
        out[(size_t)warp * OUTW + 1] = y;
    }
}

// ------------------------------------------------------------------
// GRU scan: 128 blocks x 2 batch rows, 384 threads (one per gate row),
// W_hh rows held in registers, h in smem.
// ------------------------------------------------------------------
__global__ __launch_bounds__(384, 1) void gru_kernel(const float* __restrict__ Whh,
                                                     const float* __restrict__ bhh,
                                                     const float* __restrict__ h0,
                                                     float* __restrict__ out) {
    int b0 = blockIdx.x * 2;
    int g = threadIdx.x;              // 0..383

    __shared__ __align__(16) float sh[2][HIDD];   // hidden state per batch row
    __shared__ float srz[2][256];                 // gi+gh for r,z rows
    __shared__ float sghn[2][HIDD];               // gh for n rows
    __shared__ float sgin[2][HIDD];               // gi for n rows

    float w[HIDD];
#pragma unroll
    for (int k4 = 0; k4 < HIDD / 4; k4++) {
        float4 wv = *(const float4*)(Whh + (size_t)g * HIDD + k4 * 4);
        w[k4 * 4 + 0] = wv.x; w[k4 * 4 + 1] = wv.y;
        w[k4 * 4 + 2] = wv.z; w[k4 * 4 + 3] = wv.w;
    }
    float bw = bhh[g];

    if (g < HIDD) {
        sh[0][g] = h0[(size_t)b0 * HIDD + g];
        sh[1][g] = h0[(size_t)(b0 + 1) * HIDD + g];
    }
    __syncthreads();

    for (int t = 0; t < T_; t++) {
        const float* gi0 = g_C + ((size_t)(b0 * T_ + t)) * ND + 256;
        const float* gi1 = g_C + ((size_t)((b0 + 1) * T_ + t)) * ND + 256;
        float acc0 = bw, acc1 = bw;
        const float4* h0v = (const float4*)sh[0];
        const float4* h1v = (const float4*)sh[1];
#pragma unroll
        for (int k4 = 0; k4 < HIDD / 4; k4++) {
            float4 hv0 = h0v[k4];
            float4 hv1 = h1v[k4];
            acc0 += w[k4 * 4 + 0] * hv0.x + w[k4 * 4 + 1] * hv0.y
                  + w[k4 * 4 + 2] * hv0.z + w[k4 * 4 + 3] * hv0.w;
            acc1 += w[k4 * 4 + 0] * hv1.x + w[k4 * 4 + 1] * hv1.y
                  + w[k4 * 4 + 2] * hv1.z + w[k4 * 4 + 3] * hv1.w;
        }
        float g0 = gi0[g], g1 = gi1[g];
        if (g < 256) {
            srz[0][g] = acc0 + g0;
            srz[1][g] = acc1 + g1;
        } else {
            int j = g - 256;
            sghn[0][j] = acc0; sgin[0][j] = g0;
            sghn[1][j] = acc1; sgin[1][j] = g1;
        }
        __syncthreads();
        if (g < 256) {
            int b = g >> 7, j = g & 127;
            float r = 1.f / (1.f + expf(-srz[b][j]));
            float z = 1.f / (1.f + expf(-srz[b][128 + j]));
            float n = tanhf(sgin[b][j] + r * sghn[b][j]);
            float hnew = (1.f - z) * n + z * sh[b][j];
            sh[b][j] = hnew;
            out[((size_t)((b0 + b) * T_ + t)) * OUTW + 2 + j] = hnew;
        }
        __syncthreads();
    }
}

// ------------------------------------------------------------------
extern "C" void kernel_launch(void* const* d_in, const int* in_sizes, int n_in,
                              void* d_out, int out_size) {
    const float* x     = (const float*)d_in[0];
    const float* xdemo = (const float*)d_in[1];
    const float* ft    = (const float*)d_in[2];
    const float* h0    = (const float*)d_in[3];
    const float* Wx2   = (const float*)d_in[4];
    const float* bx2   = (const float*)d_in[5];
    const float* Wst   = (const float*)d_in[6];
    const float* bst   = (const float*)d_in[7];
    const float* Wm1a  = (const float*)d_in[8];
    const float* bm1a  = (const float*)d_in[9];
    const float* Wm1b  = (const float*)d_in[10];
    const float* bm1b  = (const float*)d_in[11];
    const float* Wm2a  = (const float*)d_in[12];
    const float* bm2a  = (const float*)d_in[13];
    const float* Wm2b  = (const float*)d_in[14];
    const float* bm2b  = (const float*)d_in[15];
    const float* Wa1   = (const float*)d_in[16];
    const float* ba1   = (const float*)d_in[17];
    const float* Wa2   = (const float*)d_in[18];
    const float* Wo1   = (const float*)d_in[19];
    const float* bo1   = (const float*)d_in[20];
    const float* Wo2   = (const float*)d_in[21];
    const float* Wih   = (const float*)d_in[22];
    const float* bih   = (const float*)d_in[23];
    const float* Whh   = (const float*)d_in[24];
    const float* bhh   = (const float*)d_in[25];
    float* out = (float*)d_out;

    demo_kernel<<<(B_ * XSTAT + 255) / 256, 256>>>(xdemo, Wst, bst);
    repack_kernel<<<480, 256>>>(Wa1, ba1, Wo1, bo1, Wih, bih);
    feat_kernel<<<M_, 128>>>(x, ft, Wm1a, bm1a, Wm1b, bm1b,
                             Wm2a, bm2a, Wm2b, bm2b, Wx2, bx2);
    gemm_kernel<<<dim3(ND / BN, M_ / BM), 256>>>();
    head_kernel<<<(M_ * 32 + 255) / 256, 256>>>(Wa2, Wo2, out);
    gru_kernel<<<B_ / 2, 384>>>(Whh, bhh, h0, out);
}

// round 3
// speedup vs baseline: 1.1378x; 1.1378x over previous
#include <cuda_runtime.h>
#include <cuda_bf16.h>
#include <math.h>
#include <stdint.h>

#define B_    256
#define T_    64
#define NAG   10
#define NFEAT 4
#define XDIM  44
#define XPERM 40
#define XSTAT 10
#define HIDD  128
#define XEMBD 32
#define NHIDD 8
#define E_    90
#define M_    (B_ * T_)      // 16384
#define KD    768            // padded from 763
#define K2    1536           // [hi | lo]
#define ND    640            // 128 (a) + 128 (o) + 384 (gi)
#define OUTW  130

// ---- scratch ----
__device__ __align__(16) __nv_bfloat16 g_Ubf[(size_t)M_ * K2];   // 48 MB
__device__ __align__(16) __nv_bfloat16 g_Wbf[(size_t)ND * K2];   // 1.9 MB (n-major)
__device__ __align__(16) float g_bias[ND];
__device__ __align__(16) float g_C[(size_t)M_ * ND];             // 40 MB
__device__ __align__(16) float g_demo[B_ * XSTAT];

// ------------------------------------------------------------------ PTX helpers (base sm_103 ISA only)
__device__ __forceinline__ uint32_t smem_u32(const void* p) {
    uint32_t a;
    asm("{ .reg .u64 t; cvta.to.shared.u64 t, %1; cvt.u32.u64 %0, t; }" : "=r"(a) : "l"(p));
    return a;
}
__device__ __forceinline__ void cpasync16(uint32_t dst, const void* src) {
    asm volatile("cp.async.cg.shared.global [%0], [%1], 16;" :: "r"(dst), "l"(src) : "memory");
}
#define CP_COMMIT() asm volatile("cp.async.commit_group;" ::: "memory")
#define CP_WAIT(n)  asm volatile("cp.async.wait_group %0;" :: "n"(n) : "memory")

__device__ __forceinline__ void ldsm_x4(uint32_t& r0, uint32_t& r1, uint32_t& r2, uint32_t& r3,
                                        uint32_t addr) {
    asm volatile("ldmatrix.sync.aligned.m8n8.x4.shared.b16 {%0,%1,%2,%3}, [%4];"
                 : "=r"(r0), "=r"(r1), "=r"(r2), "=r"(r3) : "r"(addr));
}
__device__ __forceinline__ void ldsm_x2(uint32_t& r0, uint32_t& r1, uint32_t addr) {
    asm volatile("ldmatrix.sync.aligned.m8n8.x2.shared.b16 {%0,%1}, [%2];"
                 : "=r"(r0), "=r"(r1) : "r"(addr));
}
__device__ __forceinline__ void mma16816(float* d, uint32_t a0, uint32_t a1, uint32_t a2,
                                         uint32_t a3, uint32_t b0, uint32_t b1) {
    asm volatile("mma.sync.aligned.m16n8k16.row.col.f32.bf16.bf16.f32 "
                 "{%0,%1,%2,%3}, {%4,%5,%6,%7}, {%8,%9}, {%0,%1,%2,%3};"
                 : "+f"(d[0]), "+f"(d[1]), "+f"(d[2]), "+f"(d[3])
                 : "r"(a0), "r"(a1), "r"(a2), "r"(a3), "r"(b0), "r"(b1));
}

// ------------------------------------------------------------------ demo
__global__ void demo_kernel(const float* __restrict__ xd,
                            const float* __restrict__ Ws,
                            const float* __restrict__ bs) {
    int i = blockIdx.x * blockDim.x + threadIdx.x;
    if (i >= B_ * XSTAT) return;
    int b = i / XSTAT, o = i % XSTAT;
    float acc = bs[o];
#pragma unroll
    for (int k = 0; k < XSTAT; k++) acc += xd[b * XSTAT + k] * Ws[o * XSTAT + k];
    g_demo[i] = acc;
}

// ------------------------------------------------------------------ feat (writes bf16 hi/lo)
__device__ __forceinline__ float elu1(float v) { return v > 0.f ? v : expm1f(v); }
__device__ __forceinline__ void wsplit(__nv_bfloat16* u, int k, float x) {
    __nv_bfloat16 h = __float2bfloat16(x);
    u[k] = h;
    u[KD + k] = __float2bfloat16(x - __bfloat162float(h));
}

__global__ void feat_kernel(const float* __restrict__ x,
                            const float* __restrict__ ft,
                            const float* __restrict__ Wm1a, const float* __restrict__ bm1a,
                            const float* __restrict__ Wm1b, const float* __restrict__ bm1b,
                            const float* __restrict__ Wm2a, const float* __restrict__ bm2a,
                            const float* __restrict__ Wm2b, const float* __restrict__ bm2b,
                            const float* __restrict__ Wx2,  const float* __restrict__ bx2) {
    int m = blockIdx.x;
    int b = m / T_, t = m % T_;
    int tid = threadIdx.x;

    __shared__ float s_x[XDIM];
    __shared__ float s_h1a[NAG * NHIDD];
    __shared__ float s_h1[NAG * NHIDD];
    __shared__ float s_h2a[E_ * NHIDD];

    const float* xr = x + ((size_t)b * (T_ + 1) + t) * XDIM;
    if (tid < XDIM) s_x[tid] = xr[tid];
    __syncthreads();

    if (tid < NAG * NHIDD) {
        int a = tid / NHIDD, o = tid % NHIDD;
        float acc = bm1a[o];
#pragma unroll
        for (int f = 0; f < NFEAT; f++) acc += s_x[a * NFEAT + f] * Wm1a[o * NFEAT + f];
        s_h1a[tid] = elu1(acc);
    }
    __syncthreads();
    if (tid < NAG * NHIDD) {
        int a = tid / NHIDD, o = tid % NHIDD;
        float acc = bm1b[o];
#pragma unroll
        for (int k = 0; k < NHIDD; k++) acc += s_h1a[a * NHIDD + k] * Wm1b[o * NHIDD + k];
        s_h1[tid] = elu1(acc);
    }
    __syncthreads();

    for (int i = tid; i < E_ * NHIDD; i += 128) {
        int e = i / NHIDD, o = i % NHIDD;
        int r = e / (NAG - 1), jj = e % (NAG - 1);
        int s = jj < r ? jj : jj + 1;
        float acc = bm2a[o];
#pragma unroll
        for (int k = 0; k < NHIDD; k++)
            acc += s_h1[r * NHIDD + k] * Wm2a[o * 16 + k]
                 + s_h1[s * NHIDD + k] * Wm2a[o * 16 + 8 + k];
        s_h2a[i] = elu1(acc);
    }
    __syncthreads();

    __nv_bfloat16* u = g_Ubf + (size_t)m * K2;
    for (int i = tid; i < E_ * NHIDD; i += 128) {
        int e = i / NHIDD, o = i % NHIDD;
        float acc = bm2b[o];
#pragma unroll
        for (int k = 0; k < NHIDD; k++) acc += s_h2a[e * NHIDD + k] * Wm2b[o * NHIDD + k];
        wsplit(u, 43 + i, elu1(acc));
    }

    if (tid < XEMBD) {
        float acc = bx2[tid];
#pragma unroll
        for (int f = 0; f < XDIM - XPERM; f++)
            acc += s_x[XPERM + f] * Wx2[tid * (XDIM - XPERM) + f];
        wsplit(u, tid, acc);
    }
    if (tid >= XEMBD && tid < XEMBD + XSTAT)
        wsplit(u, tid, g_demo[b * XSTAT + (tid - XEMBD)]);
    if (tid == 42) wsplit(u, 42, ft[(size_t)b * (T_ + 1) + t]);
    if (tid >= 43 && tid < 48) {                 // pad 763..767 (both halves)
        u[720 + tid] = __float2bfloat16(0.f);
        u[KD + 720 + tid] = __float2bfloat16(0.f);
    }
}

// ------------------------------------------------------------------ repack W -> bf16 hi/lo, n-major
__global__ void repack_kernel(const float* __restrict__ Wa1, const float* __restrict__ ba1,
                              const float* __restrict__ Wo1, const float* __restrict__ bo1,
                              const float* __restrict__ Wih, const float* __restrict__ bih) {
    int idx = blockIdx.x * blockDim.x + threadIdx.x;
    if (idx < ND)
        g_bias[idx] = idx < 128 ? ba1[idx] : (idx < 256 ? bo1[idx - 128] : bih[idx - 256]);

    int stride = gridDim.x * blockDim.x;
    for (int i = idx; i < KD * ND; i += stride) {
        int n = i / KD, k = i % KD;
        float v = 0.f;
        if (n < 128) {
            if (k >= 32 && k < 42)       v = Wa1[n * 730 + (k - 32)];
            else if (k >= 43 && k < 763) v = Wa1[n * 730 + 10 + (k - 43)];
        } else if (n < 256) {
            if (k < 763) v = Wo1[(n - 128) * 763 + k];
        } else {
            int r = n - 256;
            if (k < 32)                  v = Wih[r * 753 + k];
            else if (k == 42)            v = Wih[r * 753 + 32];
            else if (k >= 43 && k < 763) v = Wih[r * 753 + 33 + (k - 43)];
        }
        __nv_bfloat16 h = __float2bfloat16(v);
        g_Wbf[(size_t)n * K2 + k] = h;
        g_Wbf[(size_t)n * K2 + KD + k] = __float2bfloat16(v - __bfloat162float(h));
    }
}

// ------------------------------------------------------------------ HMMA GEMM
// C[16384 x 640] = sum over 3 segments: hiU*hiW + loU*hiW + hiU*loW  (K_eff = 2304)
// CTA tile 128x128, BK=64, 8 warps each 64x32, cp.async double buffer.
#define BK      64
#define NCHUNK  36                    // 3 segments x 12 chunks of 64
#define TILEB   (128 * BK * 2)        // 16 KB per tile
#define STAGEB  (2 * TILEB)           // A+B per stage: 32 KB
#define SMEMB   (2 * STAGEB)          // 64 KB

__device__ __forceinline__ void load_chunk(uint32_t sA, uint32_t sB,
                                           int m0, int n0, int a_koff, int b_koff, int tid) {
#pragma unroll
    for (int t = 0; t < 4; t++) {
        int i = tid + t * 256;
        int row = i >> 3, cc = i & 7;
        uint32_t off = row * 128 + cc * 16;
        uint32_t sw = off ^ ((off >> 3) & 0x70);
        cpasync16(sA + sw, g_Ubf + (size_t)(m0 + row) * K2 + a_koff + cc * 8);
        cpasync16(sB + sw, g_Wbf + (size_t)(n0 + row) * K2 + b_koff + cc * 8);
    }
}

__global__ __launch_bounds__(256, 1) void gemm_hmma_kernel() {
    extern __shared__ char smem[];
    uint32_t sb = smem_u32(smem);
    int tid = threadIdx.x;
    int wid = tid >> 5, lane = tid & 31;
    int m0 = blockIdx.y * 128;
    int n0 = blockIdx.x * 128;
    int wm64 = (wid & 1) * 64;   // warp m offset
    int wn32 = (wid >> 1) * 32;  // warp n offset

    // ldmatrix per-thread row/col bases
    int arow = (lane & 7) + ((lane >> 3) & 1) * 8;
    int akc  = (lane >> 4) * 8;
    int l2   = lane & 15;
    int brow = l2 & 7;
    int bkc  = ((l2 >> 3) & 1) * 8;

    float acc[4][4][4];
#pragma unroll
    for (int mt = 0; mt < 4; mt++)
#pragma unroll
        for (int nt = 0; nt < 4; nt++)
#pragma unroll
            for (int r = 0; r < 4; r++) acc[mt][nt][r] = 0.f;

    // prologue: chunk 0 -> stage 0
    load_chunk(sb, sb + TILEB, m0, n0, 0, 0, tid);
    CP_COMMIT();

    for (int c = 0; c < NCHUNK; c++) {
        if (c + 1 < NCHUNK) {
            int cn = c + 1;
            int blk = cn / 12, w = cn % 12;
            int a_koff = (blk == 1 ? KD : 0) + w * BK;
            int b_koff = (blk == 2 ? KD : 0) + w * BK;
            uint32_t st = sb + ((cn & 1) ? STAGEB : 0);
            load_chunk(st, st + TILEB, m0, n0, a_koff, b_koff, tid);
            CP_COMMIT();
            CP_WAIT(1);
        } else {
            CP_WAIT(0);
        }
        __syncthreads();

        uint32_t sA = sb + ((c & 1) ? STAGEB : 0);
        uint32_t sB = sA + TILEB;
#pragma unroll
        for (int ks = 0; ks < 4; ks++) {
            uint32_t a[4][4];
#pragma unroll
            for (int mt = 0; mt < 4; mt++) {
                uint32_t off = (uint32_t)(wm64 + mt * 16 + arow) * 128 + (ks * 16 + akc) * 2;
                off ^= (off >> 3) & 0x70;
                ldsm_x4(a[mt][0], a[mt][1], a[mt][2], a[mt][3], sA + off);
            }
#pragma unroll
            for (int nt = 0; nt < 4; nt++) {
                uint32_t off = (uint32_t)(wn32 + nt * 8 + brow) * 128 + (ks * 16 + bkc) * 2;
                off ^= (off >> 3) & 0x70;
                uint32_t b0, b1;
                ldsm_x2(b0, b1, sB + off);
#pragma unroll
                for (int mt = 0; mt < 4; mt++)
                    mma16816(acc[mt][nt], a[mt][0], a[mt][1], a[mt][2], a[mt][3], b0, b1);
            }
        }
        __syncthreads();
    }

    // epilogue: add bias, write fp32 C
    int tq = lane >> 2, tr = lane & 3;
#pragma unroll
    for (int nt = 0; nt < 4; nt++) {
        int col = n0 + wn32 + nt * 8 + tr * 2;
        float2 bv = *(const float2*)&g_bias[col];
#pragma unroll
        for (int mt = 0; mt < 4; mt++) {
            size_t row0 = (size_t)m0 + wm64 + mt * 16 + tq;
            float2 v0 = {acc[mt][nt][0] + bv.x, acc[mt][nt][1] + bv.y};
            float2 v1 = {acc[mt][nt][2] + bv.x, acc[mt][nt][3] + bv.y};
            *(float2*)(g_C + row0 * ND + col) = v0;
            *(float2*)(g_C + (row0 + 8) * ND + col) = v1;
        }
    }
}

// ------------------------------------------------------------------ heads
__global__ void head_kernel(const float* __restrict__ Wa2,
                            const float* __restrict__ Wo2,
                            float* __restrict__ out) {
    int warp = (blockIdx.x * blockDim.x + threadIdx.x) >> 5;
    int lane = threadIdx.x & 31;
    if (warp >= M_) return;
    const float* c = g_C + (size_t)warp * ND;
    float a = 0.f, y = 0.f;
#pragma unroll
    for (int j = lane; j < 128; j += 32) {
        a += fmaxf(c[j], 0.f) * Wa2[j];
        y += fmaxf(c[128 + j], 0.f) * Wo2[j];
    }
#pragma unroll
    for (int s = 16; s; s >>= 1) {
        a += __shfl_down_sync(0xFFFFFFFFu, a, s);
        y += __shfl_down_sync(0xFFFFFFFFu, y, s);
    }
    if (lane == 0) {
        out[(size_t)warp * OUTW + 0] = a;
        out[(size_t)warp * OUTW + 1] = y;
    }
}

// ------------------------------------------------------------------ GRU scan
__global__ __launch_bounds__(384, 1) void gru_kernel(const float* __restrict__ Whh,
                                                     const float* __restrict__ bhh,
                                                     const float* __restrict__ h0,
                                                     float* __restrict__ out) {
    int b0 = blockIdx.x * 2;
    int g = threadIdx.x;

    __shared__ __align__(16) float sh[2][HIDD];
    __shared__ float srz[2][256];
    __shared__ float sghn[2][HIDD];
    __shared__ float sgin[2][HIDD];

    float w[HIDD];
#pragma unroll
    for (int k4 = 0; k4 < HIDD / 4; k4++) {
        float4 wv = *(const float4*)(Whh + (size_t)g * HIDD + k4 * 4);
        w[k4 * 4 + 0] = wv.x; w[k4 * 4 + 1] = wv.y;
        w[k4 * 4 + 2] = wv.z; w[k4 * 4 + 3] = wv.w;
    }
    float bw = bhh[g];

    if (g < HIDD) {
        sh[0][g] = h0[(size_t)b0 * HIDD + g];
        sh[1][g] = h0[(size_t)(b0 + 1) * HIDD + g];
    }
    __syncthreads();

    for (int t = 0; t < T_; t++) {
        const float* gi0 = g_C + ((size_t)(b0 * T_ + t)) * ND + 256;
        const float* gi1 = g_C + ((size_t)((b0 + 1) * T_ + t)) * ND + 256;
        float acc0 = bw, acc1 = bw;
        const float4* h0v = (const float4*)sh[0];
        const float4* h1v = (const float4*)sh[1];
#pragma unroll
        for (int k4 = 0; k4 < HIDD / 4; k4++) {
            float4 hv0 = h0v[k4];
            float4 hv1 = h1v[k4];
            acc0 += w[k4 * 4 + 0] * hv0.x + w[k4 * 4 + 1] * hv0.y
                  + w[k4 * 4 + 2] * hv0.z + w[k4 * 4 + 3] * hv0.w;
            acc1 += w[k4 * 4 + 0] * hv1.x + w[k4 * 4 + 1] * hv1.y
                  + w[k4 * 4 + 2] * hv1.z + w[k4 * 4 + 3] * hv1.w;
        }
        float g0 = gi0[g], g1 = gi1[g];
        if (g < 256) {
            srz[0][g] = acc0 + g0;
            srz[1][g] = acc1 + g1;
        } else {
            int j = g - 256;
            sghn[0][j] = acc0; sgin[0][j] = g0;
            sghn[1][j] = acc1; sgin[1][j] = g1;
        }
        __syncthreads();
        if (g < 256) {
            int b = g >> 7, j = g & 127;
            float r = 1.f / (1.f + expf(-srz[b][j]));
            float z = 1.f / (1.f + expf(-srz[b][128 + j]));
            float n = tanhf(sgin[b][j] + r * sghn[b][j]);
            float hnew = (1.f - z) * n + z * sh[b][j];
            sh[b][j] = hnew;
            out[((size_t)((b0 + b) * T_ + t)) * OUTW + 2 + j] = hnew;
        }
        __syncthreads();
    }
}

// ------------------------------------------------------------------
extern "C" void kernel_launch(void* const* d_in, const int* in_sizes, int n_in,
                              void* d_out, int out_size) {
    const float* x     = (const float*)d_in[0];
    const float* xdemo = (const float*)d_in[1];
    const float* ft    = (const float*)d_in[2];
    const float* h0    = (const float*)d_in[3];
    const float* Wx2   = (const float*)d_in[4];
    const float* bx2   = (const float*)d_in[5];
    const float* Wst   = (const float*)d_in[6];
    const float* bst   = (const float*)d_in[7];
    const float* Wm1a  = (const float*)d_in[8];
    const float* bm1a  = (const float*)d_in[9];
    const float* Wm1b  = (const float*)d_in[10];
    const float* bm1b  = (const float*)d_in[11];
    const float* Wm2a  = (const float*)d_in[12];
    const float* bm2a  = (const float*)d_in[13];
    const float* Wm2b  = (const float*)d_in[14];
    const float* bm2b  = (const float*)d_in[15];
    const float* Wa1   = (const float*)d_in[16];
    const float* ba1   = (const float*)d_in[17];
    const float* Wa2   = (const float*)d_in[18];
    const float* Wo1   = (const float*)d_in[19];
    const float* bo1   = (const float*)d_in[20];
    const float* Wo2   = (const float*)d_in[21];
    const float* Wih   = (const float*)d_in[22];
    const float* bih   = (const float*)d_in[23];
    const float* Whh   = (const float*)d_in[24];
    const float* bhh   = (const float*)d_in[25];
    float* out = (float*)d_out;

    cudaFuncSetAttribute(gemm_hmma_kernel,
                         cudaFuncAttributeMaxDynamicSharedMemorySize, SMEMB);

    demo_kernel<<<(B_ * XSTAT + 255) / 256, 256>>>(xdemo, Wst, bst);
    repack_kernel<<<480, 256>>>(Wa1, ba1, Wo1, bo1, Wih, bih);
    feat_kernel<<<M_, 128>>>(x, ft, Wm1a, bm1a, Wm1b, bm1b,
                             Wm2a, bm2a, Wm2b, bm2b, Wx2, bx2);
    gemm_hmma_kernel<<<dim3(ND / 128, M_ / 128), 256, SMEMB>>>();
    head_kernel<<<(M_ * 32 + 255) / 256, 256>>>(Wa2, Wo2, out);
    gru_kernel<<<B_ / 2, 384>>>(Whh, bhh, h0, out);
}

// round 4
// speedup vs baseline: 1.6869x; 1.4826x over previous
#include <cuda_runtime.h>
#include <cuda_bf16.h>
#include <math.h>
#include <stdint.h>

#define B_    256
#define T_    64
#define NAG   10
#define NFEAT 4
#define XDIM  44
#define XPERM 40
#define XSTAT 10
#define HIDD  128
#define XEMBD 32
#define NHIDD 8
#define E_    90
#define M_    (B_ * T_)      // 16384
#define KD    768            // padded from 763
#define K2    1536           // [hi | lo]
#define ND    640            // 128 (a) + 128 (o) + 384 (gi)
#define OUTW  130

// ---- scratch ----
__device__ __align__(16) __nv_bfloat16 g_Ubf[(size_t)M_ * K2];   // 48 MB
__device__ __align__(16) __nv_bfloat16 g_Wbf[(size_t)ND * K2];   // 1.9 MB (n-major)
__device__ __align__(16) float g_bias[ND];
__device__ __align__(16) float g_C[(size_t)M_ * ND];             // 40 MB
__device__ __align__(16) float g_demo[B_ * XSTAT];

// ------------------------------------------------------------------ PTX helpers (base sm_103 ISA)
__device__ __forceinline__ uint32_t smem_u32(const void* p) {
    uint32_t a;
    asm("{ .reg .u64 t; cvta.to.shared.u64 t, %1; cvt.u32.u64 %0, t; }" : "=r"(a) : "l"(p));
    return a;
}
__device__ __forceinline__ void cpasync16(uint32_t dst, const void* src) {
    asm volatile("cp.async.cg.shared.global [%0], [%1], 16;" :: "r"(dst), "l"(src) : "memory");
}
#define CP_COMMIT() asm volatile("cp.async.commit_group;" ::: "memory")
#define CP_WAIT(n)  asm volatile("cp.async.wait_group %0;" :: "n"(n) : "memory")

__device__ __forceinline__ void ldsm_x4(uint32_t& r0, uint32_t& r1, uint32_t& r2, uint32_t& r3,
                                        uint32_t addr) {
    asm volatile("ldmatrix.sync.aligned.m8n8.x4.shared.b16 {%0,%1,%2,%3}, [%4];"
                 : "=r"(r0), "=r"(r1), "=r"(r2), "=r"(r3) : "r"(addr));
}
__device__ __forceinline__ void ldsm_x2(uint32_t& r0, uint32_t& r1, uint32_t addr) {
    asm volatile("ldmatrix.sync.aligned.m8n8.x2.shared.b16 {%0,%1}, [%2];"
                 : "=r"(r0), "=r"(r1) : "r"(addr));
}
__device__ __forceinline__ void mma16816(float* d, uint32_t a0, uint32_t a1, uint32_t a2,
                                         uint32_t a3, uint32_t b0, uint32_t b1) {
    asm volatile("mma.sync.aligned.m16n8k16.row.col.f32.bf16.bf16.f32 "
                 "{%0,%1,%2,%3}, {%4,%5,%6,%7}, {%8,%9}, {%0,%1,%2,%3};"
                 : "+f"(d[0]), "+f"(d[1]), "+f"(d[2]), "+f"(d[3])
                 : "r"(a0), "r"(a1), "r"(a2), "r"(a3), "r"(b0), "r"(b1));
}

// ------------------------------------------------------------------ demo
__global__ void demo_kernel(const float* __restrict__ xd,
                            const float* __restrict__ Ws,
                            const float* __restrict__ bs) {
    int i = blockIdx.x * blockDim.x + threadIdx.x;
    if (i >= B_ * XSTAT) return;
    int b = i / XSTAT, o = i % XSTAT;
    float acc = bs[o];
#pragma unroll
    for (int k = 0; k < XSTAT; k++) acc += xd[b * XSTAT + k] * Ws[o * XSTAT + k];
    g_demo[i] = acc;
}

// ------------------------------------------------------------------ feat (2 timesteps per block, p1/p2 factorization)
__device__ __forceinline__ float elu1(float v) { return v > 0.f ? v : expm1f(v); }
__device__ __forceinline__ void wsplit(__nv_bfloat16* u, int k, float x) {
    __nv_bfloat16 h = __float2bfloat16(x);
    u[k] = h;
    u[KD + k] = __float2bfloat16(x - __bfloat162float(h));
}

__global__ __launch_bounds__(256) void feat_kernel(
        const float* __restrict__ x,
        const float* __restrict__ ft,
        const float* __restrict__ Wm1a, const float* __restrict__ bm1a,
        const float* __restrict__ Wm1b, const float* __restrict__ bm1b,
        const float* __restrict__ Wm2a, const float* __restrict__ bm2a,
        const float* __restrict__ Wm2b, const float* __restrict__ bm2b,
        const float* __restrict__ Wx2,  const float* __restrict__ bx2) {
    int sub = threadIdx.x >> 7;       // 0/1
    int tid = threadIdx.x & 127;
    int m = blockIdx.x * 2 + sub;
    int b = m / T_, t = m % T_;

    __shared__ float s_x[2][XDIM];
    __shared__ float s_h1a[2][NAG * NHIDD];
    __shared__ float s_h1[2][NAG * NHIDD];
    __shared__ float s_p[2][2][NAG][NHIDD];
    __shared__ float s_h2a[2][E_ * NHIDD];

    const float* xr = x + ((size_t)b * (T_ + 1) + t) * XDIM;
    if (tid < XDIM) s_x[sub][tid] = xr[tid];
    __syncthreads();

    if (tid < NAG * NHIDD) {
        int a = tid / NHIDD, o = tid % NHIDD;
        float acc = bm1a[o];
#pragma unroll
        for (int f = 0; f < NFEAT; f++) acc += s_x[sub][a * NFEAT + f] * Wm1a[o * NFEAT + f];
        s_h1a[sub][tid] = elu1(acc);
    }
    __syncthreads();
    if (tid < NAG * NHIDD) {
        int a = tid / NHIDD, o = tid % NHIDD;
        float acc = bm1b[o];
#pragma unroll
        for (int k = 0; k < NHIDD; k++) acc += s_h1a[sub][a * NHIDD + k] * Wm1b[o * NHIDD + k];
        s_h1[sub][tid] = elu1(acc);
    }
    __syncthreads();

    // p[part][a][o] = sum_k h1[a][k] * Wm2a[o][part*8+k]   (160 units)
    for (int i = tid; i < 2 * NAG * NHIDD; i += 128) {
        int part = i / (NAG * NHIDD);
        int rest = i % (NAG * NHIDD);
        int a = rest / NHIDD, o = rest % NHIDD;
        float acc = 0.f;
#pragma unroll
        for (int k = 0; k < NHIDD; k++)
            acc += s_h1[sub][a * NHIDD + k] * Wm2a[o * 16 + part * 8 + k];
        s_p[sub][part][a][o] = acc;
    }
    __syncthreads();

    // h2a[e][o] = elu(p0[recv][o] + p1[send][o] + b)
    for (int i = tid; i < E_ * NHIDD; i += 128) {
        int e = i / NHIDD, o = i % NHIDD;
        int r = e / (NAG - 1), jj = e % (NAG - 1);
        int s = jj < r ? jj : jj + 1;
        s_h2a[sub][i] = elu1(s_p[sub][0][r][o] + s_p[sub][1][s][o] + bm2a[o]);
    }
    __syncthreads();

    __nv_bfloat16* u = g_Ubf + (size_t)m * K2;
    for (int i = tid; i < E_ * NHIDD; i += 128) {
        int e = i / NHIDD, o = i % NHIDD;
        float acc = bm2b[o];
#pragma unroll
        for (int k = 0; k < NHIDD; k++) acc += s_h2a[sub][e * NHIDD + k] * Wm2b[o * NHIDD + k];
        wsplit(u, 43 + i, elu1(acc));
    }

    if (tid < XEMBD) {
        float acc = bx2[tid];
#pragma unroll
        for (int f = 0; f < XDIM - XPERM; f++)
            acc += s_x[sub][XPERM + f] * Wx2[tid * (XDIM - XPERM) + f];
        wsplit(u, tid, acc);
    }
    if (tid >= XEMBD && tid < XEMBD + XSTAT)
        wsplit(u, tid, g_demo[b * XSTAT + (tid - XEMBD)]);
    if (tid == 42) wsplit(u, 42, ft[(size_t)b * (T_ + 1) + t]);
    if (tid >= 43 && tid < 48) {                 // pad 763..767 (both halves)
        u[720 + tid] = __float2bfloat16(0.f);
        u[KD + 720 + tid] = __float2bfloat16(0.f);
    }
}

// ------------------------------------------------------------------ repack W -> bf16 hi/lo, n-major
__global__ void repack_kernel(const float* __restrict__ Wa1, const float* __restrict__ ba1,
                              const float* __restrict__ Wo1, const float* __restrict__ bo1,
                              const float* __restrict__ Wih, const float* __restrict__ bih) {
    int idx = blockIdx.x * blockDim.x + threadIdx.x;
    if (idx < ND)
        g_bias[idx] = idx < 128 ? ba1[idx] : (idx < 256 ? bo1[idx - 128] : bih[idx - 256]);

    int stride = gridDim.x * blockDim.x;
    for (int i = idx; i < KD * ND; i += stride) {
        int n = i / KD, k = i % KD;
        float v = 0.f;
        if (n < 128) {
            if (k >= 32 && k < 42)       v = Wa1[n * 730 + (k - 32)];
            else if (k >= 43 && k < 763) v = Wa1[n * 730 + 10 + (k - 43)];
        } else if (n < 256) {
            if (k < 763) v = Wo1[(n - 128) * 763 + k];
        } else {
            int r = n - 256;
            if (k < 32)                  v = Wih[r * 753 + k];
            else if (k == 42)            v = Wih[r * 753 + 32];
            else if (k >= 43 && k < 763) v = Wih[r * 753 + 33 + (k - 43)];
        }
        __nv_bfloat16 h = __float2bfloat16(v);
        g_Wbf[(size_t)n * K2 + k] = h;
        g_Wbf[(size_t)n * K2 + KD + k] = __float2bfloat16(v - __bfloat162float(h));
    }
}

// ------------------------------------------------------------------ HMMA GEMM
// C[16384 x 640] = hiU*hiW + loU*hiW + hiU*loW  (K_eff = 2304)
// CTA 128x128, BK=64, 512 threads (16 warps of 32x32), 4-stage cp.async, 1 sync/chunk.
#define BK      64
#define NCHUNK  36
#define TILEB   (128 * BK * 2)        // 16 KB
#define STAGEB  (2 * TILEB)           // 32 KB
#define NSTAGE  4
#define SMEMB   (NSTAGE * STAGEB)     // 128 KB

__device__ __forceinline__ void load_chunk(uint32_t stage, int m0, int n0,
                                           int a_koff, int b_koff, int tid) {
    uint32_t sA = stage, sB = stage + TILEB;
#pragma unroll
    for (int t = 0; t < 2; t++) {
        int i = tid + t * 512;
        int row = i >> 3, cc = i & 7;
        uint32_t off = row * 128 + cc * 16;
        uint32_t sw = off ^ ((off >> 3) & 0x70);
        cpasync16(sA + sw, g_Ubf + (size_t)(m0 + row) * K2 + a_koff + cc * 8);
        cpasync16(sB + sw, g_Wbf + (size_t)(n0 + row) * K2 + b_koff + cc * 8);
    }
}

__device__ __forceinline__ void chunk_offs(int c, int& a_koff, int& b_koff) {
    int blk = c / 12, w = c % 12;
    a_koff = (blk == 1 ? KD : 0) + w * BK;
    b_koff = (blk == 2 ? KD : 0) + w * BK;
}

__global__ __launch_bounds__(512, 1) void gemm_hmma_kernel() {
    extern __shared__ char smem[];
    uint32_t sb = smem_u32(smem);
    int tid = threadIdx.x;
    int wid = tid >> 5, lane = tid & 31;
    int m0 = blockIdx.y * 128;
    int n0 = blockIdx.x * 128;
    int wm = (wid & 3) * 32;     // warp m offset (4 tiles)
    int wn = (wid >> 2) * 32;    // warp n offset (4 tiles)

    int arow = (lane & 7) + ((lane >> 3) & 1) * 8;
    int akc  = (lane >> 4) * 8;
    int l2   = lane & 15;
    int brow = l2 & 7;
    int bkc  = ((l2 >> 3) & 1) * 8;

    float acc[2][4][4];
#pragma unroll
    for (int mt = 0; mt < 2; mt++)
#pragma unroll
        for (int nt = 0; nt < 4; nt++)
#pragma unroll
            for (int r = 0; r < 4; r++) acc[mt][nt][r] = 0.f;

    // prologue: stages 0..2 <- chunks 0..2
#pragma unroll
    for (int c = 0; c < 3; c++) {
        int ak, bk2;
        chunk_offs(c, ak, bk2);
        load_chunk(sb + c * STAGEB, m0, n0, ak, bk2, tid);
        CP_COMMIT();
    }

    for (int c = 0; c < NCHUNK; c++) {
        if (c + 3 < NCHUNK) CP_WAIT(2); else CP_WAIT(0);
        __syncthreads();
        if (c + 3 < NCHUNK) {     // safe: all warps are past compute(c-1)
            int ak, bk2;
            chunk_offs(c + 3, ak, bk2);
            load_chunk(sb + ((c + 3) & 3) * STAGEB, m0, n0, ak, bk2, tid);
            CP_COMMIT();
        }

        uint32_t sA = sb + (c & 3) * STAGEB;
        uint32_t sB = sA + TILEB;
#pragma unroll
        for (int ks = 0; ks < 4; ks++) {
            uint32_t a[2][4];
#pragma unroll
            for (int mt = 0; mt < 2; mt++) {
                uint32_t off = (uint32_t)(wm + mt * 16 + arow) * 128 + (ks * 16 + akc) * 2;
                off ^= (off >> 3) & 0x70;
                ldsm_x4(a[mt][0], a[mt][1], a[mt][2], a[mt][3], sA + off);
            }
#pragma unroll
            for (int nt = 0; nt < 4; nt++) {
                uint32_t off = (uint32_t)(wn + nt * 8 + brow) * 128 + (ks * 16 + bkc) * 2;
                off ^= (off >> 3) & 0x70;
                uint32_t b0, b1;
                ldsm_x2(b0, b1, sB + off);
#pragma unroll
                for (int mt = 0; mt < 2; mt++)
                    mma16816(acc[mt][nt], a[mt][0], a[mt][1], a[mt][2], a[mt][3], b0, b1);
            }
        }
    }

    // epilogue: add bias, write fp32 C
    int tq = lane >> 2, tr = lane & 3;
#pragma unroll
    for (int nt = 0; nt < 4; nt++) {
        int col = n0 + wn + nt * 8 + tr * 2;
        float2 bv = *(const float2*)&g_bias[col];
#pragma unroll
        for (int mt = 0; mt < 2; mt++) {
            size_t row0 = (size_t)m0 + wm + mt * 16 + tq;
            float2 v0 = {acc[mt][nt][0] + bv.x, acc[mt][nt][1] + bv.y};
            float2 v1 = {acc[mt][nt][2] + bv.x, acc[mt][nt][3] + bv.y};
            *(float2*)(g_C + row0 * ND + col) = v0;
            *(float2*)(g_C + (row0 + 8) * ND + col) = v1;
        }
    }
}

// ------------------------------------------------------------------ heads
__global__ void head_kernel(const float* __restrict__ Wa2,
                            const float* __restrict__ Wo2,
                            float* __restrict__ out) {
    int warp = (blockIdx.x * blockDim.x + threadIdx.x) >> 5;
    int lane = threadIdx.x & 31;
    if (warp >= M_) return;
    const float* c = g_C + (size_t)warp * ND;
    float a = 0.f, y = 0.f;
#pragma unroll
    for (int j = lane; j < 128; j += 32) {
        a += fmaxf(c[j], 0.f) * Wa2[j];
        y += fmaxf(c[128 + j], 0.f) * Wo2[j];
    }
#pragma unroll
    for (int s = 16; s; s >>= 1) {
        a += __shfl_down_sync(0xFFFFFFFFu, a, s);
        y += __shfl_down_sync(0xFFFFFFFFu, y, s);
    }
    if (lane == 0) {
        out[(size_t)warp * OUTW + 0] = a;
        out[(size_t)warp * OUTW + 1] = y;
    }
}

// ------------------------------------------------------------------ GRU scan
__global__ __launch_bounds__(384, 1) void gru_kernel(const float* __restrict__ Whh,
                                                     const float* __restrict__ bhh,
                                                     const float* __restrict__ h0,
                                                     float* __restrict__ out) {
    int b0 = blockIdx.x * 2;
    int g = threadIdx.x;

    __shared__ __align__(16) float sh[2][HIDD];
    __shared__ float srz[2][256];
    __shared__ float sghn[2][HIDD];
    __shared__ float sgin[2][HIDD];

    float w[HIDD];
#pragma unroll
    for (int k4 = 0; k4 < HIDD / 4; k4++) {
        float4 wv = *(const float4*)(Whh + (size_t)g * HIDD + k4 * 4);
        w[k4 * 4 + 0] = wv.x; w[k4 * 4 + 1] = wv.y;
        w[k4 * 4 + 2] = wv.z; w[k4 * 4 + 3] = wv.w;
    }
    float bw = bhh[g];

    if (g < HIDD) {
        sh[0][g] = h0[(size_t)b0 * HIDD + g];
        sh[1][g] = h0[(size_t)(b0 + 1) * HIDD + g];
    }
    __syncthreads();

    for (int t = 0; t < T_; t++) {
        const float* gi0 = g_C + ((size_t)(b0 * T_ + t)) * ND + 256;
        const float* gi1 = g_C + ((size_t)((b0 + 1) * T_ + t)) * ND + 256;
        float acc0 = bw, acc1 = bw;
        const float4* h0v = (const float4*)sh[0];
        const float4* h1v = (const float4*)sh[1];
#pragma unroll
        for (int k4 = 0; k4 < HIDD / 4; k4++) {
            float4 hv0 = h0v[k4];
            float4 hv1 = h1v[k4];
            acc0 += w[k4 * 4 + 0] * hv0.x + w[k4 * 4 + 1] * hv0.y
                  + w[k4 * 4 + 2] * hv0.z + w[k4 * 4 + 3] * hv0.w;
            acc1 += w[k4 * 4 + 0] * hv1.x + w[k4 * 4 + 1] * hv1.y
                  + w[k4 * 4 + 2] * hv1.z + w[k4 * 4 + 3] * hv1.w;
        }
        float g0 = gi0[g], g1 = gi1[g];
        if (g < 256) {
            srz[0][g] = acc0 + g0;
            srz[1][g] = acc1 + g1;
        } else {
            int j = g - 256;
            sghn[0][j] = acc0; sgin[0][j] = g0;
            sghn[1][j] = acc1; sgin[1][j] = g1;
        }
        __syncthreads();
        if (g < 256) {
            int b = g >> 7, j = g & 127;
            float r = 1.f / (1.f + expf(-srz[b][j]));
            float z = 1.f / (1.f + expf(-srz[b][128 + j]));
            float n = tanhf(sgin[b][j] + r * sghn[b][j]);
            float hnew = (1.f - z) * n + z * sh[b][j];
            sh[b][j] = hnew;
            out[((size_t)((b0 + b) * T_ + t)) * OUTW + 2 + j] = hnew;
        }
        __syncthreads();
    }
}

// ------------------------------------------------------------------
extern "C" void kernel_launch(void* const* d_in, const int* in_sizes, int n_in,
                              void* d_out, int out_size) {
    const float* x     = (const float*)d_in[0];
    const float* xdemo = (const float*)d_in[1];
    const float* ft    = (const float*)d_in[2];
    const float* h0    = (const float*)d_in[3];
    const float* Wx2   = (const float*)d_in[4];
    const float* bx2   = (const float*)d_in[5];
    const float* Wst   = (const float*)d_in[6];
    const float* bst   = (const float*)d_in[7];
    const float* Wm1a  = (const float*)d_in[8];
    const float* bm1a  = (const float*)d_in[9];
    const float* Wm1b  = (const float*)d_in[10];
    const float* bm1b  = (const float*)d_in[11];
    const float* Wm2a  = (const float*)d_in[12];
    const float* bm2a  = (const float*)d_in[13];
    const float* Wm2b  = (const float*)d_in[14];
    const float* bm2b  = (const float*)d_in[15];
    const float* Wa1   = (const float*)d_in[16];
    const float* ba1   = (const float*)d_in[17];
    const float* Wa2   = (const float*)d_in[18];
    const float* Wo1   = (const float*)d_in[19];
    const float* bo1   = (const float*)d_in[20];
    const float* Wo2   = (const float*)d_in[21];
    const float* Wih   = (const float*)d_in[22];
    const float* bih   = (const float*)d_in[23];
    const float* Whh   = (const float*)d_in[24];
    const float* bhh   = (const float*)d_in[25];
    float* out = (float*)d_out;

    cudaFuncSetAttribute(gemm_hmma_kernel,
                         cudaFuncAttributeMaxDynamicSharedMemorySize, SMEMB);

    demo_kernel<<<(B_ * XSTAT + 255) / 256, 256>>>(xdemo, Wst, bst);
    repack_kernel<<<480, 256>>>(Wa1, ba1, Wo1, bo1, Wih, bih);
    feat_kernel<<<M_ / 2, 256>>>(x, ft, Wm1a, bm1a, Wm1b, bm1b,
                                 Wm2a, bm2a, Wm2b, bm2b, Wx2, bx2);
    gemm_hmma_kernel<<<dim3(ND / 128, M_ / 128), 512, SMEMB>>>();
    head_kernel<<<(M_ * 32 + 255) / 256, 256>>>(Wa2, Wo2, out);
    gru_kernel<<<B_ / 2, 384>>>(Whh, bhh, h0, out);
}

// round 5
// speedup vs baseline: 2.7701x; 1.6422x over previous
#include <cuda_runtime.h>
#include <cuda_fp16.h>
#include <math.h>
#include <stdint.h>

#define B_    256
#define T_    64
#define NAG   10
#define NFEAT 4
#define XDIM  44
#define XPERM 40
#define XSTAT 10
#define HIDD  128
#define XEMBD 32
#define NHIDD 8
#define E_    90
#define M_    (B_ * T_)      // 16384
#define KD    768            // padded from 763
#define ND    640            // 128 (a) + 128 (o) + 384 (gi)
#define OUTW  130

// ---- scratch ----
__device__ __align__(16) __half g_Uh[(size_t)M_ * KD];    // 24 MB
__device__ __align__(16) __half g_Wh[(size_t)ND * KD];    // 0.94 MB (n-major)
__device__ __align__(16) float g_bias[ND];
__device__ __align__(16) float g_C[(size_t)M_ * ND];      // 40 MB
__device__ __align__(16) float g_demo[B_ * XSTAT];

// ------------------------------------------------------------------ PTX helpers
__device__ __forceinline__ uint32_t smem_u32(const void* p) {
    uint32_t a;
    asm("{ .reg .u64 t; cvta.to.shared.u64 t, %1; cvt.u32.u64 %0, t; }" : "=r"(a) : "l"(p));
    return a;
}
__device__ __forceinline__ void cpasync16(uint32_t dst, const void* src) {
    asm volatile("cp.async.cg.shared.global [%0], [%1], 16;" :: "r"(dst), "l"(src) : "memory");
}
#define CP_COMMIT() asm volatile("cp.async.commit_group;" ::: "memory")
#define CP_WAIT(n)  asm volatile("cp.async.wait_group %0;" :: "n"(n) : "memory")

__device__ __forceinline__ void ldsm_x4(uint32_t& r0, uint32_t& r1, uint32_t& r2, uint32_t& r3,
                                        uint32_t addr) {
    asm volatile("ldmatrix.sync.aligned.m8n8.x4.shared.b16 {%0,%1,%2,%3}, [%4];"
                 : "=r"(r0), "=r"(r1), "=r"(r2), "=r"(r3) : "r"(addr));
}
__device__ __forceinline__ void ldsm_x2(uint32_t& r0, uint32_t& r1, uint32_t addr) {
    asm volatile("ldmatrix.sync.aligned.m8n8.x2.shared.b16 {%0,%1}, [%2];"
                 : "=r"(r0), "=r"(r1) : "r"(addr));
}
__device__ __forceinline__ void mma16816(float* d, uint32_t a0, uint32_t a1, uint32_t a2,
                                         uint32_t a3, uint32_t b0, uint32_t b1) {
    asm volatile("mma.sync.aligned.m16n8k16.row.col.f32.f16.f16.f32 "
                 "{%0,%1,%2,%3}, {%4,%5,%6,%7}, {%8,%9}, {%0,%1,%2,%3};"
                 : "+f"(d[0]), "+f"(d[1]), "+f"(d[2]), "+f"(d[3])
                 : "r"(a0), "r"(a1), "r"(a2), "r"(a3), "r"(b0), "r"(b1));
}

// ------------------------------------------------------------------ demo
__global__ void demo_kernel(const float* __restrict__ xd,
                            const float* __restrict__ Ws,
                            const float* __restrict__ bs) {
    int i = blockIdx.x * blockDim.x + threadIdx.x;
    if (i >= B_ * XSTAT) return;
    int b = i / XSTAT, o = i % XSTAT;
    float acc = bs[o];
#pragma unroll
    for (int k = 0; k < XSTAT; k++) acc += xd[b * XSTAT + k] * Ws[o * XSTAT + k];
    g_demo[i] = acc;
}

// ------------------------------------------------------------------ feat (2 timesteps/block, p1/p2 factorization)
__device__ __forceinline__ float elu1(float v) { return v > 0.f ? v : expm1f(v); }

__global__ __launch_bounds__(256) void feat_kernel(
        const float* __restrict__ x,
        const float* __restrict__ ft,
        const float* __restrict__ Wm1a, const float* __restrict__ bm1a,
        const float* __restrict__ Wm1b, const float* __restrict__ bm1b,
        const float* __restrict__ Wm2a, const float* __restrict__ bm2a,
        const float* __restrict__ Wm2b, const float* __restrict__ bm2b,
        const float* __restrict__ Wx2,  const float* __restrict__ bx2) {
    int sub = threadIdx.x >> 7;
    int tid = threadIdx.x & 127;
    int m = blockIdx.x * 2 + sub;
    int b = m / T_, t = m % T_;

    __shared__ float s_x[2][XDIM];
    __shared__ float s_h1a[2][NAG * NHIDD];
    __shared__ float s_h1[2][NAG * NHIDD];
    __shared__ float s_p[2][2][NAG][NHIDD];
    __shared__ float s_h2a[2][E_ * NHIDD];

    const float* xr = x + ((size_t)b * (T_ + 1) + t) * XDIM;
    if (tid < XDIM) s_x[sub][tid] = xr[tid];
    __syncthreads();

    if (tid < NAG * NHIDD) {
        int a = tid / NHIDD, o = tid % NHIDD;
        float acc = bm1a[o];
#pragma unroll
        for (int f = 0; f < NFEAT; f++) acc += s_x[sub][a * NFEAT + f] * Wm1a[o * NFEAT + f];
        s_h1a[sub][tid] = elu1(acc);
    }
    __syncthreads();
    if (tid < NAG * NHIDD) {
        int a = tid / NHIDD, o = tid % NHIDD;
        float acc = bm1b[o];
#pragma unroll
        for (int k = 0; k < NHIDD; k++) acc += s_h1a[sub][a * NHIDD + k] * Wm1b[o * NHIDD + k];
        s_h1[sub][tid] = elu1(acc);
    }
    __syncthreads();

    for (int i = tid; i < 2 * NAG * NHIDD; i += 128) {
        int part = i / (NAG * NHIDD);
        int rest = i % (NAG * NHIDD);
        int a = rest / NHIDD, o = rest % NHIDD;
        float acc = 0.f;
#pragma unroll
        for (int k = 0; k < NHIDD; k++)
            acc += s_h1[sub][a * NHIDD + k] * Wm2a[o * 16 + part * 8 + k];
        s_p[sub][part][a][o] = acc;
    }
    __syncthreads();

    for (int i = tid; i < E_ * NHIDD; i += 128) {
        int e = i / NHIDD, o = i % NHIDD;
        int r = e / (NAG - 1), jj = e % (NAG - 1);
        int s = jj < r ? jj : jj + 1;
        s_h2a[sub][i] = elu1(s_p[sub][0][r][o] + s_p[sub][1][s][o] + bm2a[o]);
    }
    __syncthreads();

    __half* u = g_Uh + (size_t)m * KD;
    for (int i = tid; i < E_ * NHIDD; i += 128) {
        int e = i / NHIDD, o = i % NHIDD;
        float acc = bm2b[o];
#pragma unroll
        for (int k = 0; k < NHIDD; k++) acc += s_h2a[sub][e * NHIDD + k] * Wm2b[o * NHIDD + k];
        u[43 + i] = __float2half(elu1(acc));
    }

    if (tid < XEMBD) {
        float acc = bx2[tid];
#pragma unroll
        for (int f = 0; f < XDIM - XPERM; f++)
            acc += s_x[sub][XPERM + f] * Wx2[tid * (XDIM - XPERM) + f];
        u[tid] = __float2half(acc);
    }
    if (tid >= XEMBD && tid < XEMBD + XSTAT)
        u[tid] = __float2half(g_demo[b * XSTAT + (tid - XEMBD)]);
    if (tid == 42) u[42] = __float2half(ft[(size_t)b * (T_ + 1) + t]);
    if (tid >= 43 && tid < 48) u[720 + tid] = __float2half(0.f);   // pad 763..767
}

// ------------------------------------------------------------------ repack W -> fp16, n-major
__global__ void repack_kernel(const float* __restrict__ Wa1, const float* __restrict__ ba1,
                              const float* __restrict__ Wo1, const float* __restrict__ bo1,
                              const float* __restrict__ Wih, const float* __restrict__ bih) {
    int idx = blockIdx.x * blockDim.x + threadIdx.x;
    if (idx < ND)
        g_bias[idx] = idx < 128 ? ba1[idx] : (idx < 256 ? bo1[idx - 128] : bih[idx - 256]);

    int stride = gridDim.x * blockDim.x;
    for (int i = idx; i < KD * ND; i += stride) {
        int n = i / KD, k = i % KD;
        float v = 0.f;
        if (n < 128) {
            if (k >= 32 && k < 42)       v = Wa1[n * 730 + (k - 32)];
            else if (k >= 43 && k < 763) v = Wa1[n * 730 + 10 + (k - 43)];
        } else if (n < 256) {
            if (k < 763) v = Wo1[(n - 128) * 763 + k];
        } else {
            int r = n - 256;
            if (k < 32)                  v = Wih[r * 753 + k];
            else if (k == 42)            v = Wih[r * 753 + 32];
            else if (k >= 43 && k < 763) v = Wih[r * 753 + 33 + (k - 43)];
        }
        g_Wh[(size_t)n * KD + k] = __float2half(v);
    }
}

// ------------------------------------------------------------------ HMMA GEMM (single-pass fp16, K=768)
#define BK      64
#define NCHUNK  (KD / BK)             // 12
#define TILEB   (128 * BK * 2)        // 16 KB
#define STAGEB  (2 * TILEB)           // 32 KB
#define NSTAGE  4
#define SMEMB   (NSTAGE * STAGEB)     // 128 KB

__device__ __forceinline__ void load_chunk(uint32_t stage, int m0, int n0,
                                           int koff, int tid) {
    uint32_t sA = stage, sB = stage + TILEB;
#pragma unroll
    for (int t = 0; t < 2; t++) {
        int i = tid + t * 512;
        int row = i >> 3, cc = i & 7;
        uint32_t off = row * 128 + cc * 16;
        uint32_t sw = off ^ ((off >> 3) & 0x70);
        cpasync16(sA + sw, g_Uh + (size_t)(m0 + row) * KD + koff + cc * 8);
        cpasync16(sB + sw, g_Wh + (size_t)(n0 + row) * KD + koff + cc * 8);
    }
}

__global__ __launch_bounds__(512, 1) void gemm_hmma_kernel() {
    extern __shared__ char smem[];
    uint32_t sb = smem_u32(smem);
    int tid = threadIdx.x;
    int wid = tid >> 5, lane = tid & 31;
    int m0 = blockIdx.y * 128;
    int n0 = blockIdx.x * 128;
    int wm = (wid & 3) * 32;
    int wn = (wid >> 2) * 32;

    int arow = (lane & 7) + ((lane >> 3) & 1) * 8;
    int akc  = (lane >> 4) * 8;
    int l2   = lane & 15;
    int brow = l2 & 7;
    int bkc  = ((l2 >> 3) & 1) * 8;

    float acc[2][4][4];
#pragma unroll
    for (int mt = 0; mt < 2; mt++)
#pragma unroll
        for (int nt = 0; nt < 4; nt++)
#pragma unroll
            for (int r = 0; r < 4; r++) acc[mt][nt][r] = 0.f;

#pragma unroll
    for (int c = 0; c < 3; c++) {
        load_chunk(sb + c * STAGEB, m0, n0, c * BK, tid);
        CP_COMMIT();
    }

    for (int c = 0; c < NCHUNK; c++) {
        if (c + 3 < NCHUNK) CP_WAIT(2); else CP_WAIT(0);
        __syncthreads();
        if (c + 3 < NCHUNK) {
            load_chunk(sb + ((c + 3) & 3) * STAGEB, m0, n0, (c + 3) * BK, tid);
            CP_COMMIT();
        }

        uint32_t sA = sb + (c & 3) * STAGEB;
        uint32_t sB = sA + TILEB;
#pragma unroll
        for (int ks = 0; ks < 4; ks++) {
            uint32_t a[2][4];
#pragma unroll
            for (int mt = 0; mt < 2; mt++) {
                uint32_t off = (uint32_t)(wm + mt * 16 + arow) * 128 + (ks * 16 + akc) * 2;
                off ^= (off >> 3) & 0x70;
                ldsm_x4(a[mt][0], a[mt][1], a[mt][2], a[mt][3], sA + off);
            }
#pragma unroll
            for (int nt = 0; nt < 4; nt++) {
                uint32_t off = (uint32_t)(wn + nt * 8 + brow) * 128 + (ks * 16 + bkc) * 2;
                off ^= (off >> 3) & 0x70;
                uint32_t b0, b1;
                ldsm_x2(b0, b1, sB + off);
#pragma unroll
                for (int mt = 0; mt < 2; mt++)
                    mma16816(acc[mt][nt], a[mt][0], a[mt][1], a[mt][2], a[mt][3], b0, b1);
            }
        }
    }

    int tq = lane >> 2, tr = lane & 3;
#pragma unroll
    for (int nt = 0; nt < 4; nt++) {
        int col = n0 + wn + nt * 8 + tr * 2;
        float2 bv = *(const float2*)&g_bias[col];
#pragma unroll
        for (int mt = 0; mt < 2; mt++) {
            size_t row0 = (size_t)m0 + wm + mt * 16 + tq;
            float2 v0 = {acc[mt][nt][0] + bv.x, acc[mt][nt][1] + bv.y};
            float2 v1 = {acc[mt][nt][2] + bv.x, acc[mt][nt][3] + bv.y};
            *(float2*)(g_C + row0 * ND + col) = v0;
            *(float2*)(g_C + (row0 + 8) * ND + col) = v1;
        }
    }
}

// ------------------------------------------------------------------ heads
__global__ void head_kernel(const float* __restrict__ Wa2,
                            const float* __restrict__ Wo2,
                            float* __restrict__ out) {
    int warp = (blockIdx.x * blockDim.x + threadIdx.x) >> 5;
    int lane = threadIdx.x & 31;
    if (warp >= M_) return;
    const float* c = g_C + (size_t)warp * ND;
    float a = 0.f, y = 0.f;
#pragma unroll
    for (int j = lane; j < 128; j += 32) {
        a += fmaxf(c[j], 0.f) * Wa2[j];
        y += fmaxf(c[128 + j], 0.f) * Wo2[j];
    }
#pragma unroll
    for (int s = 16; s; s >>= 1) {
        a += __shfl_down_sync(0xFFFFFFFFu, a, s);
        y += __shfl_down_sync(0xFFFFFFFFu, y, s);
    }
    if (lane == 0) {
        out[(size_t)warp * OUTW + 0] = a;
        out[(size_t)warp * OUTW + 1] = y;
    }
}

// ------------------------------------------------------------------ GRU scan (gi prefetch)
__global__ __launch_bounds__(384, 1) void gru_kernel(const float* __restrict__ Whh,
                                                     const float* __restrict__ bhh,
                                                     const float* __restrict__ h0,
                                                     float* __restrict__ out) {
    int b0 = blockIdx.x * 2;
    int g = threadIdx.x;

    __shared__ __align__(16) float sh[2][HIDD];
    __shared__ float srz[2][256];
    __shared__ float sghn[2][HIDD];
    __shared__ float sgin[2][HIDD];

    float w[HIDD];
#pragma unroll
    for (int k4 = 0; k4 < HIDD / 4; k4++) {
        float4 wv = *(const float4*)(Whh + (size_t)g * HIDD + k4 * 4);
        w[k4 * 4 + 0] = wv.x; w[k4 * 4 + 1] = wv.y;
        w[k4 * 4 + 2] = wv.z; w[k4 * 4 + 3] = wv.w;
    }
    float bw = bhh[g];

    if (g < HIDD) {
        sh[0][g] = h0[(size_t)b0 * HIDD + g];
        sh[1][g] = h0[(size_t)(b0 + 1) * HIDD + g];
    }

    const float* gi0 = g_C + ((size_t)(b0 * T_)) * ND + 256;
    const float* gi1 = g_C + ((size_t)((b0 + 1) * T_)) * ND + 256;
    float gc0 = gi0[g], gc1 = gi1[g];
    __syncthreads();

    for (int t = 0; t < T_; t++) {
        float gn0, gn1;
        if (t + 1 < T_) {                 // prefetch next timestep's gi
            gn0 = gi0[(size_t)(t + 1) * ND + g];
            gn1 = gi1[(size_t)(t + 1) * ND + g];
        }
        float acc0 = bw, acc1 = bw;
        const float4* h0v = (const float4*)sh[0];
        const float4* h1v = (const float4*)sh[1];
#pragma unroll
        for (int k4 = 0; k4 < HIDD / 4; k4++) {
            float4 hv0 = h0v[k4];
            float4 hv1 = h1v[k4];
            acc0 += w[k4 * 4 + 0] * hv0.x + w[k4 * 4 + 1] * hv0.y
                  + w[k4 * 4 + 2] * hv0.z + w[k4 * 4 + 3] * hv0.w;
            acc1 += w[k4 * 4 + 0] * hv1.x + w[k4 * 4 + 1] * hv1.y
                  + w[k4 * 4 + 2] * hv1.z + w[k4 * 4 + 3] * hv1.w;
        }
        if (g < 256) {
            srz[0][g] = acc0 + gc0;
            srz[1][g] = acc1 + gc1;
        } else {
            int j = g - 256;
            sghn[0][j] = acc0; sgin[0][j] = gc0;
            sghn[1][j] = acc1; sgin[1][j] = gc1;
        }
        __syncthreads();
        if (g < 256) {
            int b = g >> 7, j = g & 127;
            float r = 1.f / (1.f + __expf(-srz[b][j]));
            float z = 1.f / (1.f + __expf(-srz[b][128 + j]));
            float n = tanhf(sgin[b][j] + r * sghn[b][j]);
            float hnew = (1.f - z) * n + z * sh[b][j];
            sh[b][j] = hnew;
            out[((size_t)((b0 + b) * T_ + t)) * OUTW + 2 + j] = hnew;
        }
        __syncthreads();
        gc0 = gn0; gc1 = gn1;
    }
}

// ------------------------------------------------------------------
extern "C" void kernel_launch(void* const* d_in, const int* in_sizes, int n_in,
                              void* d_out, int out_size) {
    const float* x     = (const float*)d_in[0];
    const float* xdemo = (const float*)d_in[1];
    const float* ft    = (const float*)d_in[2];
    const float* h0    = (const float*)d_in[3];
    const float* Wx2   = (const float*)d_in[4];
    const float* bx2   = (const float*)d_in[5];
    const float* Wst   = (const float*)d_in[6];
    const float* bst   = (const float*)d_in[7];
    const float* Wm1a  = (const float*)d_in[8];
    const float* bm1a  = (const float*)d_in[9];
    const float* Wm1b  = (const float*)d_in[10];
    const float* bm1b  = (const float*)d_in[11];
    const float* Wm2a  = (const float*)d_in[12];
    const float* bm2a  = (const float*)d_in[13];
    const float* Wm2b  = (const float*)d_in[14];
    const float* bm2b  = (const float*)d_in[15];
    const float* Wa1   = (const float*)d_in[16];
    const float* ba1   = (const float*)d_in[17];
    const float* Wa2   = (const float*)d_in[18];
    const float* Wo1   = (const float*)d_in[19];
    const float* bo1   = (const float*)d_in[20];
    const float* Wo2   = (const float*)d_in[21];
    const float* Wih   = (const float*)d_in[22];
    const float* bih   = (const float*)d_in[23];
    const float* Whh   = (const float*)d_in[24];
    const float* bhh   = (const float*)d_in[25];
    float* out = (float*)d_out;

    cudaFuncSetAttribute(gemm_hmma_kernel,
                         cudaFuncAttributeMaxDynamicSharedMemorySize, SMEMB);

    demo_kernel<<<(B_ * XSTAT + 255) / 256, 256>>>(xdemo, Wst, bst);
    repack_kernel<<<480, 256>>>(Wa1, ba1, Wo1, bo1, Wih, bih);
    feat_kernel<<<M_ / 2, 256>>>(x, ft, Wm1a, bm1a, Wm1b, bm1b,
                                 Wm2a, bm2a, Wm2b, bm2b, Wx2, bx2);
    gemm_hmma_kernel<<<dim3(ND / 128, M_ / 128), 512, SMEMB>>>();
    head_kernel<<<(M_ * 32 + 255) / 256, 256>>>(Wa2, Wo2, out);
    gru_kernel<<<B_ / 2, 384>>>(Whh, bhh, h0, out);
}

// round 6
// speedup vs baseline: 2.8976x; 1.0460x over previous
#include <cuda_runtime.h>
#include <cuda_fp16.h>
#include <math.h>
#include <stdint.h>

#define B_    256
#define T_    64
#define NAG   10
#define NFEAT 4
#define XDIM  44
#define XPERM 40
#define XSTAT 10
#define HIDD  128
#define XEMBD 32
#define NHIDD 8
#define E_    90
#define M_    (B_ * T_)      // 16384
#define KD    768            // padded from 763
#define ND    640            // 128 (a) + 128 (o) + 384 (gi)
#define OUTW  130

// ---- scratch ----
__device__ __align__(16) __half g_Uh[(size_t)M_ * KD];    // 24 MB
__device__ __align__(16) __half g_Wh[(size_t)ND * KD];    // 0.94 MB (n-major)
__device__ __align__(16) float g_bias[ND];
__device__ __align__(16) float g_C[(size_t)M_ * ND];      // 40 MB
__device__ __align__(16) float g_demo[B_ * XSTAT];

// ------------------------------------------------------------------ PTX helpers
__device__ __forceinline__ uint32_t smem_u32(const void* p) {
    uint32_t a;
    asm("{ .reg .u64 t; cvta.to.shared.u64 t, %1; cvt.u32.u64 %0, t; }" : "=r"(a) : "l"(p));
    return a;
}
__device__ __forceinline__ void cpasync16(uint32_t dst, const void* src) {
    asm volatile("cp.async.cg.shared.global [%0], [%1], 16;" :: "r"(dst), "l"(src) : "memory");
}
#define CP_COMMIT() asm volatile("cp.async.commit_group;" ::: "memory")
#define CP_WAIT(n)  asm volatile("cp.async.wait_group %0;" :: "n"(n) : "memory")

__device__ __forceinline__ void ldsm_x4(uint32_t& r0, uint32_t& r1, uint32_t& r2, uint32_t& r3,
                                        uint32_t addr) {
    asm volatile("ldmatrix.sync.aligned.m8n8.x4.shared.b16 {%0,%1,%2,%3}, [%4];"
                 : "=r"(r0), "=r"(r1), "=r"(r2), "=r"(r3) : "r"(addr));
}
__device__ __forceinline__ void ldsm_x2(uint32_t& r0, uint32_t& r1, uint32_t addr) {
    asm volatile("ldmatrix.sync.aligned.m8n8.x2.shared.b16 {%0,%1}, [%2];"
                 : "=r"(r0), "=r"(r1) : "r"(addr));
}
__device__ __forceinline__ void mma16816(float* d, uint32_t a0, uint32_t a1, uint32_t a2,
                                         uint32_t a3, uint32_t b0, uint32_t b1) {
    asm volatile("mma.sync.aligned.m16n8k16.row.col.f32.f16.f16.f32 "
                 "{%0,%1,%2,%3}, {%4,%5,%6,%7}, {%8,%9}, {%0,%1,%2,%3};"
                 : "+f"(d[0]), "+f"(d[1]), "+f"(d[2]), "+f"(d[3])
                 : "r"(a0), "r"(a1), "r"(a2), "r"(a3), "r"(b0), "r"(b1));
}
__device__ __forceinline__ float tanh_fast(float x) {
    float y;
    asm("tanh.approx.f32 %0, %1;" : "=f"(y) : "f"(x));
    return y;
}

// ------------------------------------------------------------------ demo
__global__ void demo_kernel(const float* __restrict__ xd,
                            const float* __restrict__ Ws,
                            const float* __restrict__ bs) {
    int i = blockIdx.x * blockDim.x + threadIdx.x;
    if (i >= B_ * XSTAT) return;
    int b = i / XSTAT, o = i % XSTAT;
    float acc = bs[o];
#pragma unroll
    for (int k = 0; k < XSTAT; k++) acc += xd[b * XSTAT + k] * Ws[o * XSTAT + k];
    g_demo[i] = acc;
}

// ------------------------------------------------------------------ feat: one WARP per (b,t), warp-scope sync only
__device__ __forceinline__ float elu1(float v) { return v > 0.f ? __expf(v) * 0.f + v : __expf(v) - 1.f; }
// note: positive branch returns v; negative uses fast exp

#define FWARPS 8   // warps per block

struct FeatScratch {
    float x[XDIM];
    float h1[NAG * NHIDD];
    float p[2][NAG][NHIDD];
    float h2a[E_ * NHIDD];
};

__global__ __launch_bounds__(FWARPS * 32) void feat_kernel(
        const float* __restrict__ x,
        const float* __restrict__ ft,
        const float* __restrict__ Wm1a, const float* __restrict__ bm1a,
        const float* __restrict__ Wm1b, const float* __restrict__ bm1b,
        const float* __restrict__ Wm2a, const float* __restrict__ bm2a,
        const float* __restrict__ Wm2b, const float* __restrict__ bm2b,
        const float* __restrict__ Wx2,  const float* __restrict__ bx2) {
    __shared__ FeatScratch sc[FWARPS];
    int w = threadIdx.x >> 5;
    int lane = threadIdx.x & 31;
    int m = blockIdx.x * FWARPS + w;
    int b = m / T_, t = m % T_;
    FeatScratch& s = sc[w];

    const float* xr = x + ((size_t)b * (T_ + 1) + t) * XDIM;
    if (lane < 32) s.x[lane] = xr[lane];
    if (lane < XDIM - 32) s.x[32 + lane] = xr[32 + lane];
    __syncwarp();

    // h1a -> h1 (80 outputs each); keep h1a in registers per-lane trick:
    float h1a_reg[3];
#pragma unroll
    for (int ii = 0; ii < 3; ii++) {
        int i = lane + ii * 32;
        if (i < NAG * NHIDD) {
            int a = i / NHIDD, o = i % NHIDD;
            float acc = bm1a[o];
#pragma unroll
            for (int f = 0; f < NFEAT; f++) acc += s.x[a * NFEAT + f] * Wm1a[o * NFEAT + f];
            h1a_reg[ii] = elu1(acc);
        }
    }
    // write h1a to smem (reuse h1 buffer), sync, then compute h1
#pragma unroll
    for (int ii = 0; ii < 3; ii++) {
        int i = lane + ii * 32;
        if (i < NAG * NHIDD) s.h1[i] = h1a_reg[ii];
    }
    __syncwarp();
    float h1_reg[3];
#pragma unroll
    for (int ii = 0; ii < 3; ii++) {
        int i = lane + ii * 32;
        if (i < NAG * NHIDD) {
            int a = i / NHIDD, o = i % NHIDD;
            float acc = bm1b[o];
#pragma unroll
            for (int k = 0; k < NHIDD; k++) acc += s.h1[a * NHIDD + k] * Wm1b[o * NHIDD + k];
            h1_reg[ii] = elu1(acc);
        }
    }
    __syncwarp();
#pragma unroll
    for (int ii = 0; ii < 3; ii++) {
        int i = lane + ii * 32;
        if (i < NAG * NHIDD) s.h1[i] = h1_reg[ii];
    }
    __syncwarp();

    // p[part][a][o] (160 outputs)
#pragma unroll
    for (int ii = 0; ii < 5; ii++) {
        int i = lane + ii * 32;
        int part = i / (NAG * NHIDD);
        int rest = i % (NAG * NHIDD);
        int a = rest / NHIDD, o = rest % NHIDD;
        float acc = 0.f;
#pragma unroll
        for (int k = 0; k < NHIDD; k++)
            acc += s.h1[a * NHIDD + k] * Wm2a[o * 16 + part * 8 + k];
        s.p[part][a][o] = acc;
    }
    __syncwarp();

    // h2a (720 outputs)
    for (int i = lane; i < E_ * NHIDD; i += 32) {
        int e = i / NHIDD, o = i % NHIDD;
        int r = e / (NAG - 1), jj = e % (NAG - 1);
        int sd = jj < r ? jj : jj + 1;
        s.h2a[i] = elu1(s.p[0][r][o] + s.p[1][sd][o] + bm2a[o]);
    }
    __syncwarp();

    // m2b + write gemb to U (720 outputs)
    __half* u = g_Uh + (size_t)m * KD;
    for (int i = lane; i < E_ * NHIDD; i += 32) {
        int e = i / NHIDD, o = i % NHIDD;
        float acc = bm2b[o];
#pragma unroll
        for (int k = 0; k < NHIDD; k++) acc += s.h2a[e * NHIDD + k] * Wm2b[o * NHIDD + k];
        u[43 + i] = __float2half(elu1(acc));
    }

    // xemb (32 outputs)
    {
        float acc = bx2[lane];
#pragma unroll
        for (int f = 0; f < XDIM - XPERM; f++)
            acc += s.x[XPERM + f] * Wx2[lane * (XDIM - XPERM) + f];
        u[lane] = __float2half(acc);
    }
    if (lane < XSTAT) u[XEMBD + lane] = __float2half(g_demo[b * XSTAT + lane]);
    if (lane == 10)   u[42] = __float2half(ft[(size_t)b * (T_ + 1) + t]);
    if (lane >= 11 && lane < 16) u[752 + lane] = __float2half(0.f);   // pad 763..767
}

// ------------------------------------------------------------------ repack W -> fp16, n-major
__global__ void repack_kernel(const float* __restrict__ Wa1, const float* __restrict__ ba1,
                              const float* __restrict__ Wo1, const float* __restrict__ bo1,
                              const float* __restrict__ Wih, const float* __restrict__ bih) {
    int idx = blockIdx.x * blockDim.x + threadIdx.x;
    if (idx < ND)
        g_bias[idx] = idx < 128 ? ba1[idx] : (idx < 256 ? bo1[idx - 128] : bih[idx - 256]);

    int stride = gridDim.x * blockDim.x;
    for (int i = idx; i < KD * ND; i += stride) {
        int n = i / KD, k = i % KD;
        float v = 0.f;
        if (n < 128) {
            if (k >= 32 && k < 42)       v = Wa1[n * 730 + (k - 32)];
            else if (k >= 43 && k < 763) v = Wa1[n * 730 + 10 + (k - 43)];
        } else if (n < 256) {
            if (k < 763) v = Wo1[(n - 128) * 763 + k];
        } else {
            int r = n - 256;
            if (k < 32)                  v = Wih[r * 753 + k];
            else if (k == 42)            v = Wih[r * 753 + 32];
            else if (k >= 43 && k < 763) v = Wih[r * 753 + 33 + (k - 43)];
        }
        g_Wh[(size_t)n * KD + k] = __float2half(v);
    }
}

// ------------------------------------------------------------------ HMMA GEMM (fp16, K=768) — unchanged from R5
#define BK      64
#define NCHUNK  (KD / BK)             // 12
#define TILEB   (128 * BK * 2)        // 16 KB
#define STAGEB  (2 * TILEB)           // 32 KB
#define NSTAGE  4
#define SMEMB   (NSTAGE * STAGEB)     // 128 KB

__device__ __forceinline__ void load_chunk(uint32_t stage, int m0, int n0,
                                           int koff, int tid) {
    uint32_t sA = stage, sB = stage + TILEB;
#pragma unroll
    for (int t = 0; t < 2; t++) {
        int i = tid + t * 512;
        int row = i >> 3, cc = i & 7;
        uint32_t off = row * 128 + cc * 16;
        uint32_t sw = off ^ ((off >> 3) & 0x70);
        cpasync16(sA + sw, g_Uh + (size_t)(m0 + row) * KD + koff + cc * 8);
        cpasync16(sB + sw, g_Wh + (size_t)(n0 + row) * KD + koff + cc * 8);
    }
}

__global__ __launch_bounds__(512, 1) void gemm_hmma_kernel() {
    extern __shared__ char smem[];
    uint32_t sb = smem_u32(smem);
    int tid = threadIdx.x;
    int wid = tid >> 5, lane = tid & 31;
    int m0 = blockIdx.y * 128;
    int n0 = blockIdx.x * 128;
    int wm = (wid & 3) * 32;
    int wn = (wid >> 2) * 32;

    int arow = (lane & 7) + ((lane >> 3) & 1) * 8;
    int akc  = (lane >> 4) * 8;
    int l2   = lane & 15;
    int brow = l2 & 7;
    int bkc  = ((l2 >> 3) & 1) * 8;

    float acc[2][4][4];
#pragma unroll
    for (int mt = 0; mt < 2; mt++)
#pragma unroll
        for (int nt = 0; nt < 4; nt++)
#pragma unroll
            for (int r = 0; r < 4; r++) acc[mt][nt][r] = 0.f;

#pragma unroll
    for (int c = 0; c < 3; c++) {
        load_chunk(sb + c * STAGEB, m0, n0, c * BK, tid);
        CP_COMMIT();
    }

    for (int c = 0; c < NCHUNK; c++) {
        if (c + 3 < NCHUNK) CP_WAIT(2); else CP_WAIT(0);
        __syncthreads();
        if (c + 3 < NCHUNK) {
            load_chunk(sb + ((c + 3) & 3) * STAGEB, m0, n0, (c + 3) * BK, tid);
            CP_COMMIT();
        }

        uint32_t sA = sb + (c & 3) * STAGEB;
        uint32_t sB = sA + TILEB;
#pragma unroll
        for (int ks = 0; ks < 4; ks++) {
            uint32_t a[2][4];
#pragma unroll
            for (int mt = 0; mt < 2; mt++) {
                uint32_t off = (uint32_t)(wm + mt * 16 + arow) * 128 + (ks * 16 + akc) * 2;
                off ^= (off >> 3) & 0x70;
                ldsm_x4(a[mt][0], a[mt][1], a[mt][2], a[mt][3], sA + off);
            }
#pragma unroll
            for (int nt = 0; nt < 4; nt++) {
                uint32_t off = (uint32_t)(wn + nt * 8 + brow) * 128 + (ks * 16 + bkc) * 2;
                off ^= (off >> 3) & 0x70;
                uint32_t b0, b1;
                ldsm_x2(b0, b1, sB + off);
#pragma unroll
                for (int mt = 0; mt < 2; mt++)
                    mma16816(acc[mt][nt], a[mt][0], a[mt][1], a[mt][2], a[mt][3], b0, b1);
            }
        }
    }

    int tq = lane >> 2, tr = lane & 3;
#pragma unroll
    for (int nt = 0; nt < 4; nt++) {
        int col = n0 + wn + nt * 8 + tr * 2;
        float2 bv = *(const float2*)&g_bias[col];
#pragma unroll
        for (int mt = 0; mt < 2; mt++) {
            size_t row0 = (size_t)m0 + wm + mt * 16 + tq;
            float2 v0 = {acc[mt][nt][0] + bv.x, acc[mt][nt][1] + bv.y};
            float2 v1 = {acc[mt][nt][2] + bv.x, acc[mt][nt][3] + bv.y};
            *(float2*)(g_C + row0 * ND + col) = v0;
            *(float2*)(g_C + (row0 + 8) * ND + col) = v1;
        }
    }
}

// ------------------------------------------------------------------ heads
__global__ void head_kernel(const float* __restrict__ Wa2,
                            const float* __restrict__ Wo2,
                            float* __restrict__ out) {
    int warp = (blockIdx.x * blockDim.x + threadIdx.x) >> 5;
    int lane = threadIdx.x & 31;
    if (warp >= M_) return;
    const float* c = g_C + (size_t)warp * ND;
    float a = 0.f, y = 0.f;
#pragma unroll
    for (int j = lane; j < 128; j += 32) {
        a += fmaxf(c[j], 0.f) * Wa2[j];
        y += fmaxf(c[128 + j], 0.f) * Wo2[j];
    }
#pragma unroll
    for (int s = 16; s; s >>= 1) {
        a += __shfl_down_sync(0xFFFFFFFFu, a, s);
        y += __shfl_down_sync(0xFFFFFFFFu, y, s);
    }
    if (lane == 0) {
        out[(size_t)warp * OUTW + 0] = a;
        out[(size_t)warp * OUTW + 1] = y;
    }
}

// ------------------------------------------------------------------ GRU scan (4-way split accumulators, fast tanh)
__global__ __launch_bounds__(384, 1) void gru_kernel(const float* __restrict__ Whh,
                                                     const float* __restrict__ bhh,
                                                     const float* __restrict__ h0,
                                                     float* __restrict__ out) {
    int b0 = blockIdx.x * 2;
    int g = threadIdx.x;

    __shared__ __align__(16) float sh[2][HIDD];
    __shared__ float srz[2][256];
    __shared__ float sghn[2][HIDD];
    __shared__ float sgin[2][HIDD];

    float w[HIDD];
#pragma unroll
    for (int k4 = 0; k4 < HIDD / 4; k4++) {
        float4 wv = *(const float4*)(Whh + (size_t)g * HIDD + k4 * 4);
        w[k4 * 4 + 0] = wv.x; w[k4 * 4 + 1] = wv.y;
        w[k4 * 4 + 2] = wv.z; w[k4 * 4 + 3] = wv.w;
    }
    float bw = bhh[g];

    if (g < HIDD) {
        sh[0][g] = h0[(size_t)b0 * HIDD + g];
        sh[1][g] = h0[(size_t)(b0 + 1) * HIDD + g];
    }

    const float* gi0 = g_C + ((size_t)(b0 * T_)) * ND + 256;
    const float* gi1 = g_C + ((size_t)((b0 + 1) * T_)) * ND + 256;
    float gc0 = gi0[g], gc1 = gi1[g];
    __syncthreads();

    for (int t = 0; t < T_; t++) {
        float gn0, gn1;
        if (t + 1 < T_) {
            gn0 = gi0[(size_t)(t + 1) * ND + g];
            gn1 = gi1[(size_t)(t + 1) * ND + g];
        }
        // 4 independent accumulator chains per row -> chain depth 32
        float a0[4] = {0.f, 0.f, 0.f, 0.f};
        float a1[4] = {0.f, 0.f, 0.f, 0.f};
        const float4* h0v = (const float4*)sh[0];
        const float4* h1v = (const float4*)sh[1];
#pragma unroll
        for (int k4 = 0; k4 < HIDD / 4; k4++) {
            float4 hv0 = h0v[k4];
            float4 hv1 = h1v[k4];
            int s = k4 & 3;
            a0[s] += w[k4 * 4 + 0] * hv0.x + w[k4 * 4 + 1] * hv0.y
                   + w[k4 * 4 + 2] * hv0.z + w[k4 * 4 + 3] * hv0.w;
            a1[s] += w[k4 * 4 + 0] * hv1.x + w[k4 * 4 + 1] * hv1.y
                   + w[k4 * 4 + 2] * hv1.z + w[k4 * 4 + 3] * hv1.w;
        }
        float acc0 = bw + ((a0[0] + a0[1]) + (a0[2] + a0[3]));
        float acc1 = bw + ((a1[0] + a1[1]) + (a1[2] + a1[3]));
        if (g < 256) {
            srz[0][g] = acc0 + gc0;
            srz[1][g] = acc1 + gc1;
        } else {
            int j = g - 256;
            sghn[0][j] = acc0; sgin[0][j] = gc0;
            sghn[1][j] = acc1; sgin[1][j] = gc1;
        }
        __syncthreads();
        if (g < 256) {
            int b = g >> 7, j = g & 127;
            float r = 1.f / (1.f + __expf(-srz[b][j]));
            float z = 1.f / (1.f + __expf(-srz[b][128 + j]));
            float n = tanh_fast(sgin[b][j] + r * sghn[b][j]);
            float hnew = (1.f - z) * n + z * sh[b][j];
            sh[b][j] = hnew;
            out[((size_t)((b0 + b) * T_ + t)) * OUTW + 2 + j] = hnew;
        }
        __syncthreads();
        gc0 = gn0; gc1 = gn1;
    }
}

// ------------------------------------------------------------------
extern "C" void kernel_launch(void* const* d_in, const int* in_sizes, int n_in,
                              void* d_out, int out_size) {
    const float* x     = (const float*)d_in[0];
    const float* xdemo = (const float*)d_in[1];
    const float* ft    = (const float*)d_in[2];
    const float* h0    = (const float*)d_in[3];
    const float* Wx2   = (const float*)d_in[4];
    const float* bx2   = (const float*)d_in[5];
    const float* Wst   = (const float*)d_in[6];
    const float* bst   = (const float*)d_in[7];
    const float* Wm1a  = (const float*)d_in[8];
    const float* bm1a  = (const float*)d_in[9];
    const float* Wm1b  = (const float*)d_in[10];
    const float* bm1b  = (const float*)d_in[11];
    const float* Wm2a  = (const float*)d_in[12];
    const float* bm2a  = (const float*)d_in[13];
    const float* Wm2b  = (const float*)d_in[14];
    const float* bm2b  = (const float*)d_in[15];
    const float* Wa1   = (const float*)d_in[16];
    const float* ba1   = (const float*)d_in[17];
    const float* Wa2   = (const float*)d_in[18];
    const float* Wo1   = (const float*)d_in[19];
    const float* bo1   = (const float*)d_in[20];
    const float* Wo2   = (const float*)d_in[21];
    const float* Wih   = (const float*)d_in[22];
    const float* bih   = (const float*)d_in[23];
    const float* Whh   = (const float*)d_in[24];
    const float* bhh   = (const float*)d_in[25];
    float* out = (float*)d_out;

    cudaFuncSetAttribute(gemm_hmma_kernel,
                         cudaFuncAttributeMaxDynamicSharedMemorySize, SMEMB);

    demo_kernel<<<(B_ * XSTAT + 255) / 256, 256>>>(xdemo, Wst, bst);
    repack_kernel<<<480, 256>>>(Wa1, ba1, Wo1, bo1, Wih, bih);
    feat_kernel<<<M_ / FWARPS, FWARPS * 32>>>(x, ft, Wm1a, bm1a, Wm1b, bm1b,
                                              Wm2a, bm2a, Wm2b, bm2b, Wx2, bx2);
    gemm_hmma_kernel<<<dim3(ND / 128, M_ / 128), 512, SMEMB>>>();
    head_kernel<<<(M_ * 32 + 255) / 256, 256>>>(Wa2, Wo2, out);
    gru_kernel<<<B_ / 2, 384>>>(Whh, bhh, h0, out);
}

// round 7
// speedup vs baseline: 3.0455x; 1.0510x over previous
#include <cuda_runtime.h>
#include <cuda_fp16.h>
#include <math.h>
#include <stdint.h>

#define B_    256
#define T_    64
#define NAG   10
#define NFEAT 4
#define XDIM  44
#define XPERM 40
#define XSTAT 10
#define HIDD  128
#define XEMBD 32
#define NHIDD 8
#define E_    90
#define M_    (B_ * T_)      // 16384
#define KD    768            // padded from 763
#define ND    640            // logical: 128 (a) + 128 (o) + 384 (gi)
#define GID   384            // stored C width (gi only)
#define OUTW  130

// ---- scratch ----
__device__ __align__(16) __half g_Uh[(size_t)M_ * KD];    // 24 MB
__device__ __align__(16) __half g_Wh[(size_t)ND * KD];    // 0.94 MB (n-major)
__device__ __align__(16) float g_bias[ND];
__device__ __align__(16) float g_C[(size_t)M_ * GID];     // 25 MB (gi only)

// ------------------------------------------------------------------ PTX helpers
__device__ __forceinline__ uint32_t smem_u32(const void* p) {
    uint32_t a;
    asm("{ .reg .u64 t; cvta.to.shared.u64 t, %1; cvt.u32.u64 %0, t; }" : "=r"(a) : "l"(p));
    return a;
}
__device__ __forceinline__ void cpasync16(uint32_t dst, const void* src) {
    asm volatile("cp.async.cg.shared.global [%0], [%1], 16;" :: "r"(dst), "l"(src) : "memory");
}
#define CP_COMMIT() asm volatile("cp.async.commit_group;" ::: "memory")
#define CP_WAIT(n)  asm volatile("cp.async.wait_group %0;" :: "n"(n) : "memory")

__device__ __forceinline__ void ldsm_x4(uint32_t& r0, uint32_t& r1, uint32_t& r2, uint32_t& r3,
                                        uint32_t addr) {
    asm volatile("ldmatrix.sync.aligned.m8n8.x4.shared.b16 {%0,%1,%2,%3}, [%4];"
                 : "=r"(r0), "=r"(r1), "=r"(r2), "=r"(r3) : "r"(addr));
}
__device__ __forceinline__ void ldsm_x2(uint32_t& r0, uint32_t& r1, uint32_t addr) {
    asm volatile("ldmatrix.sync.aligned.m8n8.x2.shared.b16 {%0,%1}, [%2];"
                 : "=r"(r0), "=r"(r1) : "r"(addr));
}
__device__ __forceinline__ void mma16816(float* d, uint32_t a0, uint32_t a1, uint32_t a2,
                                         uint32_t a3, uint32_t b0, uint32_t b1) {
    asm volatile("mma.sync.aligned.m16n8k16.row.col.f32.f16.f16.f32 "
                 "{%0,%1,%2,%3}, {%4,%5,%6,%7}, {%8,%9}, {%0,%1,%2,%3};"
                 : "+f"(d[0]), "+f"(d[1]), "+f"(d[2]), "+f"(d[3])
                 : "r"(a0), "r"(a1), "r"(a2), "r"(a3), "r"(b0), "r"(b1));
}
__device__ __forceinline__ float tanh_fast(float x) {
    float y;
    asm("tanh.approx.f32 %0, %1;" : "=f"(y) : "f"(x));
    return y;
}

// ------------------------------------------------------------------ feat: one WARP per (b,t); demo fused in
__device__ __forceinline__ float elu1(float v) { return v > 0.f ? v : __expf(v) - 1.f; }

#define FWARPS 8

struct FeatScratch {
    float x[XDIM];
    float h1[NAG * NHIDD];
    float p[2][NAG][NHIDD];
    float h2a[E_ * NHIDD];
};

__global__ __launch_bounds__(FWARPS * 32) void feat_kernel(
        const float* __restrict__ x,
        const float* __restrict__ ft,
        const float* __restrict__ xd,   const float* __restrict__ Wst,
        const float* __restrict__ bst,
        const float* __restrict__ Wm1a, const float* __restrict__ bm1a,
        const float* __restrict__ Wm1b, const float* __restrict__ bm1b,
        const float* __restrict__ Wm2a, const float* __restrict__ bm2a,
        const float* __restrict__ Wm2b, const float* __restrict__ bm2b,
        const float* __restrict__ Wx2,  const float* __restrict__ bx2) {
    __shared__ FeatScratch sc[FWARPS];
    int w = threadIdx.x >> 5;
    int lane = threadIdx.x & 31;
    int m = blockIdx.x * FWARPS + w;
    int b = m / T_, t = m % T_;
    FeatScratch& s = sc[w];

    const float* xr = x + ((size_t)b * (T_ + 1) + t) * XDIM;
    s.x[lane] = xr[lane];
    if (lane < XDIM - 32) s.x[32 + lane] = xr[32 + lane];
    __syncwarp();

    float h1a_reg[3];
#pragma unroll
    for (int ii = 0; ii < 3; ii++) {
        int i = lane + ii * 32;
        if (i < NAG * NHIDD) {
            int a = i / NHIDD, o = i % NHIDD;
            float acc = bm1a[o];
#pragma unroll
            for (int f = 0; f < NFEAT; f++) acc += s.x[a * NFEAT + f] * Wm1a[o * NFEAT + f];
            h1a_reg[ii] = elu1(acc);
        }
    }
#pragma unroll
    for (int ii = 0; ii < 3; ii++) {
        int i = lane + ii * 32;
        if (i < NAG * NHIDD) s.h1[i] = h1a_reg[ii];
    }
    __syncwarp();
    float h1_reg[3];
#pragma unroll
    for (int ii = 0; ii < 3; ii++) {
        int i = lane + ii * 32;
        if (i < NAG * NHIDD) {
            int a = i / NHIDD, o = i % NHIDD;
            float acc = bm1b[o];
#pragma unroll
            for (int k = 0; k < NHIDD; k++) acc += s.h1[a * NHIDD + k] * Wm1b[o * NHIDD + k];
            h1_reg[ii] = elu1(acc);
        }
    }
    __syncwarp();
#pragma unroll
    for (int ii = 0; ii < 3; ii++) {
        int i = lane + ii * 32;
        if (i < NAG * NHIDD) s.h1[i] = h1_reg[ii];
    }
    __syncwarp();

#pragma unroll
    for (int ii = 0; ii < 5; ii++) {
        int i = lane + ii * 32;
        int part = i / (NAG * NHIDD);
        int rest = i % (NAG * NHIDD);
        int a = rest / NHIDD, o = rest % NHIDD;
        float acc = 0.f;
#pragma unroll
        for (int k = 0; k < NHIDD; k++)
            acc += s.h1[a * NHIDD + k] * Wm2a[o * 16 + part * 8 + k];
        s.p[part][a][o] = acc;
    }
    __syncwarp();

    for (int i = lane; i < E_ * NHIDD; i += 32) {
        int e = i / NHIDD, o = i % NHIDD;
        int r = e / (NAG - 1), jj = e % (NAG - 1);
        int sd = jj < r ? jj : jj + 1;
        s.h2a[i] = elu1(s.p[0][r][o] + s.p[1][sd][o] + bm2a[o]);
    }
    __syncwarp();

    __half* u = g_Uh + (size_t)m * KD;
    for (int i = lane; i < E_ * NHIDD; i += 32) {
        int e = i / NHIDD, o = i % NHIDD;
        float acc = bm2b[o];
#pragma unroll
        for (int k = 0; k < NHIDD; k++) acc += s.h2a[e * NHIDD + k] * Wm2b[o * NHIDD + k];
        u[43 + i] = __float2half(elu1(acc));
    }

    // xemb
    {
        float acc = bx2[lane];
#pragma unroll
        for (int f = 0; f < XDIM - XPERM; f++)
            acc += s.x[XPERM + f] * Wx2[lane * (XDIM - XPERM) + f];
        u[lane] = __float2half(acc);
    }
    // demo (recomputed per warp: 10 outputs x 10 MAC)
    if (lane < XSTAT) {
        float acc = bst[lane];
        const float* xdr = xd + (size_t)b * XSTAT;
#pragma unroll
        for (int k = 0; k < XSTAT; k++) acc += xdr[k] * Wst[lane * XSTAT + k];
        u[XEMBD + lane] = __float2half(acc);
    }
    if (lane == 10) u[42] = __float2half(ft[(size_t)b * (T_ + 1) + t]);
    if (lane >= 11 && lane < 16) u[752 + lane] = __float2half(0.f);   // pad 763..767
}

// ------------------------------------------------------------------ repack W -> fp16, n-major; zero out[:,0:2]
__global__ void repack_kernel(const float* __restrict__ Wa1, const float* __restrict__ ba1,
                              const float* __restrict__ Wo1, const float* __restrict__ bo1,
                              const float* __restrict__ Wih, const float* __restrict__ bih,
                              float* __restrict__ out) {
    int idx = blockIdx.x * blockDim.x + threadIdx.x;
    if (idx < ND)
        g_bias[idx] = idx < 128 ? ba1[idx] : (idx < 256 ? bo1[idx - 128] : bih[idx - 256]);

    int stride = gridDim.x * blockDim.x;
    for (int i = idx; i < 2 * M_; i += stride)
        out[(size_t)(i >> 1) * OUTW + (i & 1)] = 0.f;

    for (int i = idx; i < KD * ND; i += stride) {
        int n = i / KD, k = i % KD;
        float v = 0.f;
        if (n < 128) {
            if (k >= 32 && k < 42)       v = Wa1[n * 730 + (k - 32)];
            else if (k >= 43 && k < 763) v = Wa1[n * 730 + 10 + (k - 43)];
        } else if (n < 256) {
            if (k < 763) v = Wo1[(n - 128) * 763 + k];
        } else {
            int r = n - 256;
            if (k < 32)                  v = Wih[r * 753 + k];
            else if (k == 42)            v = Wih[r * 753 + 32];
            else if (k >= 43 && k < 763) v = Wih[r * 753 + 33 + (k - 43)];
        }
        g_Wh[(size_t)n * KD + k] = __float2half(v);
    }
}

// ------------------------------------------------------------------ HMMA GEMM (fp16, K=768), heads fused into epilogue
#define BK      64
#define NCHUNK  (KD / BK)             // 12
#define TILEB   (128 * BK * 2)        // 16 KB
#define STAGEB  (2 * TILEB)           // 32 KB
#define NSTAGE  4
#define SMEMB   (NSTAGE * STAGEB)     // 128 KB

__device__ __forceinline__ void load_chunk(uint32_t stage, int m0, int n0,
                                           int koff, int tid) {
    uint32_t sA = stage, sB = stage + TILEB;
#pragma unroll
    for (int t = 0; t < 2; t++) {
        int i = tid + t * 512;
        int row = i >> 3, cc = i & 7;
        uint32_t off = row * 128 + cc * 16;
        uint32_t sw = off ^ ((off >> 3) & 0x70);
        cpasync16(sA + sw, g_Uh + (size_t)(m0 + row) * KD + koff + cc * 8);
        cpasync16(sB + sw, g_Wh + (size_t)(n0 + row) * KD + koff + cc * 8);
    }
}

__global__ __launch_bounds__(512, 1) void gemm_hmma_kernel(
        const float* __restrict__ Wa2, const float* __restrict__ Wo2,
        float* __restrict__ out) {
    extern __shared__ char smem[];
    uint32_t sb = smem_u32(smem);
    int tid = threadIdx.x;
    int wid = tid >> 5, lane = tid & 31;
    int m0 = blockIdx.y * 128;
    int n0 = blockIdx.x * 128;
    int wm = (wid & 3) * 32;
    int wn = (wid >> 2) * 32;

    int arow = (lane & 7) + ((lane >> 3) & 1) * 8;
    int akc  = (lane >> 4) * 8;
    int l2   = lane & 15;
    int brow = l2 & 7;
    int bkc  = ((l2 >> 3) & 1) * 8;

    float acc[2][4][4];
#pragma unroll
    for (int mt = 0; mt < 2; mt++)
#pragma unroll
        for (int nt = 0; nt < 4; nt++)
#pragma unroll
            for (int r = 0; r < 4; r++) acc[mt][nt][r] = 0.f;

#pragma unroll
    for (int c = 0; c < 3; c++) {
        load_chunk(sb + c * STAGEB, m0, n0, c * BK, tid);
        CP_COMMIT();
    }

    for (int c = 0; c < NCHUNK; c++) {
        if (c + 3 < NCHUNK) CP_WAIT(2); else CP_WAIT(0);
        __syncthreads();
        if (c + 3 < NCHUNK) {
            load_chunk(sb + ((c + 3) & 3) * STAGEB, m0, n0, (c + 3) * BK, tid);
            CP_COMMIT();
        }

        uint32_t sA = sb + (c & 3) * STAGEB;
        uint32_t sB = sA + TILEB;
#pragma unroll
        for (int ks = 0; ks < 4; ks++) {
            uint32_t a[2][4];
#pragma unroll
            for (int mt = 0; mt < 2; mt++) {
                uint32_t off = (uint32_t)(wm + mt * 16 + arow) * 128 + (ks * 16 + akc) * 2;
                off ^= (off >> 3) & 0x70;
                ldsm_x4(a[mt][0], a[mt][1], a[mt][2], a[mt][3], sA + off);
            }
#pragma unroll
            for (int nt = 0; nt < 4; nt++) {
                uint32_t off = (uint32_t)(wn + nt * 8 + brow) * 128 + (ks * 16 + bkc) * 2;
                off ^= (off >> 3) & 0x70;
                uint32_t b0, b1;
                ldsm_x2(b0, b1, sB + off);
#pragma unroll
                for (int mt = 0; mt < 2; mt++)
                    mma16816(acc[mt][nt], a[mt][0], a[mt][1], a[mt][2], a[mt][3], b0, b1);
            }
        }
    }

    int tq = lane >> 2, tr = lane & 3;

    if (blockIdx.x >= 2) {
        // gi tiles: bias + store to g_C (width GID, col base n0-256)
        int cb = n0 - 256;
#pragma unroll
        for (int nt = 0; nt < 4; nt++) {
            int col = wn + nt * 8 + tr * 2;
            float2 bv = *(const float2*)&g_bias[n0 + col];
#pragma unroll
            for (int mt = 0; mt < 2; mt++) {
                size_t row0 = (size_t)m0 + wm + mt * 16 + tq;
                float2 v0 = {acc[mt][nt][0] + bv.x, acc[mt][nt][1] + bv.y};
                float2 v1 = {acc[mt][nt][2] + bv.x, acc[mt][nt][3] + bv.y};
                *(float2*)(g_C + row0 * GID + cb + col) = v0;
                *(float2*)(g_C + (row0 + 8) * GID + cb + col) = v1;
            }
        }
    } else {
        // head tiles: bias + relu + dot with w2, atomicAdd into out[:, blockIdx.x]
        const float* w2 = blockIdx.x == 0 ? Wa2 : Wo2;
        int hid = blockIdx.x;   // 0 -> a_out, 1 -> y_out
        float part[2][2] = {{0.f, 0.f}, {0.f, 0.f}};   // [mt][row half]
#pragma unroll
        for (int nt = 0; nt < 4; nt++) {
            int col = wn + nt * 8 + tr * 2;
            float2 bv = *(const float2*)&g_bias[n0 + col];
            float w0 = w2[col], w1 = w2[col + 1];
#pragma unroll
            for (int mt = 0; mt < 2; mt++) {
                part[mt][0] += fmaxf(acc[mt][nt][0] + bv.x, 0.f) * w0
                             + fmaxf(acc[mt][nt][1] + bv.y, 0.f) * w1;
                part[mt][1] += fmaxf(acc[mt][nt][2] + bv.x, 0.f) * w0
                             + fmaxf(acc[mt][nt][3] + bv.y, 0.f) * w1;
            }
        }
        // reduce across tr (lanes differing in bits 0..1)
#pragma unroll
        for (int mt = 0; mt < 2; mt++)
#pragma unroll
            for (int h = 0; h < 2; h++) {
                part[mt][h] += __shfl_xor_sync(0xFFFFFFFFu, part[mt][h], 1);
                part[mt][h] += __shfl_xor_sync(0xFFFFFFFFu, part[mt][h], 2);
            }
        if (tr == 0) {
#pragma unroll
            for (int mt = 0; mt < 2; mt++) {
                size_t row0 = (size_t)m0 + wm + mt * 16 + tq;
                atomicAdd(out + row0 * OUTW + hid, part[mt][0]);
                atomicAdd(out + (row0 + 8) * OUTW + hid, part[mt][1]);
            }
        }
    }
}

// ------------------------------------------------------------------ GRU scan
__global__ __launch_bounds__(384, 1) void gru_kernel(const float* __restrict__ Whh,
                                                     const float* __restrict__ bhh,
                                                     const float* __restrict__ h0,
                                                     float* __restrict__ out) {
    int b0 = blockIdx.x * 2;
    int g = threadIdx.x;

    __shared__ __align__(16) float sh[2][HIDD];
    __shared__ float srz[2][256];
    __shared__ float sghn[2][HIDD];
    __shared__ float sgin[2][HIDD];

    float w[HIDD];
#pragma unroll
    for (int k4 = 0; k4 < HIDD / 4; k4++) {
        float4 wv = *(const float4*)(Whh + (size_t)g * HIDD + k4 * 4);
        w[k4 * 4 + 0] = wv.x; w[k4 * 4 + 1] = wv.y;
        w[k4 * 4 + 2] = wv.z; w[k4 * 4 + 3] = wv.w;
    }
    float bw = bhh[g];

    if (g < HIDD) {
        sh[0][g] = h0[(size_t)b0 * HIDD + g];
        sh[1][g] = h0[(size_t)(b0 + 1) * HIDD + g];
    }

    const float* gi0 = g_C + ((size_t)(b0 * T_)) * GID;
    const float* gi1 = g_C + ((size_t)((b0 + 1) * T_)) * GID;
    float gc0 = gi0[g], gc1 = gi1[g];
    __syncthreads();

    for (int t = 0; t < T_; t++) {
        float gn0, gn1;
        if (t + 1 < T_) {
            gn0 = gi0[(size_t)(t + 1) * GID + g];
            gn1 = gi1[(size_t)(t + 1) * GID + g];
        }
        float a0[4] = {0.f, 0.f, 0.f, 0.f};
        float a1[4] = {0.f, 0.f, 0.f, 0.f};
        const float4* h0v = (const float4*)sh[0];
        const float4* h1v = (const float4*)sh[1];
#pragma unroll
        for (int k4 = 0; k4 < HIDD / 4; k4++) {
            float4 hv0 = h0v[k4];
            float4 hv1 = h1v[k4];
            int s = k4 & 3;
            a0[s] += w[k4 * 4 + 0] * hv0.x + w[k4 * 4 + 1] * hv0.y
                   + w[k4 * 4 + 2] * hv0.z + w[k4 * 4 + 3] * hv0.w;
            a1[s] += w[k4 * 4 + 0] * hv1.x + w[k4 * 4 + 1] * hv1.y
                   + w[k4 * 4 + 2] * hv1.z + w[k4 * 4 + 3] * hv1.w;
        }
        float acc0 = bw + ((a0[0] + a0[1]) + (a0[2] + a0[3]));
        float acc1 = bw + ((a1[0] + a1[1]) + (a1[2] + a1[3]));
        if (g < 256) {
            srz[0][g] = acc0 + gc0;
            srz[1][g] = acc1 + gc1;
        } else {
            int j = g - 256;
            sghn[0][j] = acc0; sgin[0][j] = gc0;
            sghn[1][j] = acc1; sgin[1][j] = gc1;
        }
        __syncthreads();
        if (g < 256) {
            int b = g >> 7, j = g & 127;
            float r = 1.f / (1.f + __expf(-srz[b][j]));
            float z = 1.f / (1.f + __expf(-srz[b][128 + j]));
            float n = tanh_fast(sgin[b][j] + r * sghn[b][j]);
            float hnew = (1.f - z) * n + z * sh[b][j];
            sh[b][j] = hnew;
            out[((size_t)((b0 + b) * T_ + t)) * OUTW + 2 + j] = hnew;
        }
        __syncthreads();
        gc0 = gn0; gc1 = gn1;
    }
}

// ------------------------------------------------------------------
extern "C" void kernel_launch(void* const* d_in, const int* in_sizes, int n_in,
                              void* d_out, int out_size) {
    const float* x     = (const float*)d_in[0];
    const float* xdemo = (const float*)d_in[1];
    const float* ft    = (const float*)d_in[2];
    const float* h0    = (const float*)d_in[3];
    const float* Wx2   = (const float*)d_in[4];
    const float* bx2   = (const float*)d_in[5];
    const float* Wst   = (const float*)d_in[6];
    const float* bst   = (const float*)d_in[7];
    const float* Wm1a  = (const float*)d_in[8];
    const float* bm1a  = (const float*)d_in[9];
    const float* Wm1b  = (const float*)d_in[10];
    const float* bm1b  = (const float*)d_in[11];
    const float* Wm2a  = (const float*)d_in[12];
    const float* bm2a  = (const float*)d_in[13];
    const float* Wm2b  = (const float*)d_in[14];
    const float* bm2b  = (const float*)d_in[15];
    const float* Wa1   = (const float*)d_in[16];
    const float* ba1   = (const float*)d_in[17];
    const float* Wa2   = (const float*)d_in[18];
    const float* Wo1   = (const float*)d_in[19];
    const float* bo1   = (const float*)d_in[20];
    const float* Wo2   = (const float*)d_in[21];
    const float* Wih   = (const float*)d_in[22];
    const float* bih   = (const float*)d_in[23];
    const float* Whh   = (const float*)d_in[24];
    const float* bhh   = (const float*)d_in[25];
    float* out = (float*)d_out;

    cudaFuncSetAttribute(gemm_hmma_kernel,
                         cudaFuncAttributeMaxDynamicSharedMemorySize, SMEMB);

    repack_kernel<<<480, 256>>>(Wa1, ba1, Wo1, bo1, Wih, bih, out);
    feat_kernel<<<M_ / FWARPS, FWARPS * 32>>>(x, ft, xdemo, Wst, bst,
                                              Wm1a, bm1a, Wm1b, bm1b,
                                              Wm2a, bm2a, Wm2b, bm2b, Wx2, bx2);
    gemm_hmma_kernel<<<dim3(ND / 128, M_ / 128), 512, SMEMB>>>(Wa2, Wo2, out);
    gru_kernel<<<B_ / 2, 384>>>(Whh, bhh, h0, out);
}

// round 8
// speedup vs baseline: 3.4182x; 1.1224x over previous
#include <cuda_runtime.h>
#include <cuda_fp16.h>
#include <math.h>
#include <stdint.h>

#define B_    256
#define T_    64
#define NAG   10
#define NFEAT 4
#define XDIM  44
#define XPERM 40
#define XSTAT 10
#define HIDD  128
#define XEMBD 32
#define NHIDD 8
#define E_    90
#define M_    (B_ * T_)      // 16384
#define KD    768            // padded from 763
#define ND    640            // logical: 128 (a) + 128 (o) + 384 (gi)
#define GID   384            // stored C width (gi only)
#define OUTW  130

// ---- scratch ----
__device__ __align__(16) __half g_Uh[(size_t)M_ * KD];    // 24 MB
__device__ __align__(16) __half g_Wh[(size_t)ND * KD];    // 0.94 MB (n-major)
__device__ __align__(16) float g_bias[ND];
__device__ __align__(16) float g_C[(size_t)M_ * GID];     // 25 MB (gi only)

// ------------------------------------------------------------------ PTX helpers
__device__ __forceinline__ uint32_t smem_u32(const void* p) {
    uint32_t a;
    asm("{ .reg .u64 t; cvta.to.shared.u64 t, %1; cvt.u32.u64 %0, t; }" : "=r"(a) : "l"(p));
    return a;
}
__device__ __forceinline__ void cpasync16(uint32_t dst, const void* src) {
    asm volatile("cp.async.cg.shared.global [%0], [%1], 16;" :: "r"(dst), "l"(src) : "memory");
}
#define CP_COMMIT() asm volatile("cp.async.commit_group;" ::: "memory")
#define CP_WAIT(n)  asm volatile("cp.async.wait_group %0;" :: "n"(n) : "memory")

__device__ __forceinline__ void ldsm_x4(uint32_t& r0, uint32_t& r1, uint32_t& r2, uint32_t& r3,
                                        uint32_t addr) {
    asm volatile("ldmatrix.sync.aligned.m8n8.x4.shared.b16 {%0,%1,%2,%3}, [%4];"
                 : "=r"(r0), "=r"(r1), "=r"(r2), "=r"(r3) : "r"(addr));
}
__device__ __forceinline__ void ldsm_x2(uint32_t& r0, uint32_t& r1, uint32_t addr) {
    asm volatile("ldmatrix.sync.aligned.m8n8.x2.shared.b16 {%0,%1}, [%2];"
                 : "=r"(r0), "=r"(r1) : "r"(addr));
}
__device__ __forceinline__ void mma16816(float* d, uint32_t a0, uint32_t a1, uint32_t a2,
                                         uint32_t a3, uint32_t b0, uint32_t b1) {
    asm volatile("mma.sync.aligned.m16n8k16.row.col.f32.f16.f16.f32 "
                 "{%0,%1,%2,%3}, {%4,%5,%6,%7}, {%8,%9}, {%0,%1,%2,%3};"
                 : "+f"(d[0]), "+f"(d[1]), "+f"(d[2]), "+f"(d[3])
                 : "r"(a0), "r"(a1), "r"(a2), "r"(a3), "r"(b0), "r"(b1));
}
__device__ __forceinline__ float tanh_fast(float x) {
    float y;
    asm("tanh.approx.f32 %0, %1;" : "=f"(y) : "f"(x));
    return y;
}
__device__ __forceinline__ float sig_fast(float x) {
    return 0.5f + 0.5f * tanh_fast(0.5f * x);
}
// pack two f32 -> f16x2 (lo = first arg)
__device__ __forceinline__ uint32_t f2h2(float lo, float hi) {
    uint32_t r;
    asm("cvt.rn.f16x2.f32 %0, %2, %1;" : "=r"(r) : "f"(lo), "f"(hi));
    return r;
}

// ------------------------------------------------------------------ feat: one WARP per (b,t); demo fused in
__device__ __forceinline__ float elu1(float v) { return v > 0.f ? v : __expf(v) - 1.f; }

#define FWARPS 8

struct FeatScratch {
    float x[XDIM];
    float h1[NAG * NHIDD];
    float p[2][NAG][NHIDD];
    float h2a[E_ * NHIDD];
};

__global__ __launch_bounds__(FWARPS * 32) void feat_kernel(
        const float* __restrict__ x,
        const float* __restrict__ ft,
        const float* __restrict__ xd,   const float* __restrict__ Wst,
        const float* __restrict__ bst,
        const float* __restrict__ Wm1a, const float* __restrict__ bm1a,
        const float* __restrict__ Wm1b, const float* __restrict__ bm1b,
        const float* __restrict__ Wm2a, const float* __restrict__ bm2a,
        const float* __restrict__ Wm2b, const float* __restrict__ bm2b,
        const float* __restrict__ Wx2,  const float* __restrict__ bx2) {
    __shared__ FeatScratch sc[FWARPS];
    int w = threadIdx.x >> 5;
    int lane = threadIdx.x & 31;
    int m = blockIdx.x * FWARPS + w;
    int b = m / T_, t = m % T_;
    FeatScratch& s = sc[w];

    const float* xr = x + ((size_t)b * (T_ + 1) + t) * XDIM;
    s.x[lane] = xr[lane];
    if (lane < XDIM - 32) s.x[32 + lane] = xr[32 + lane];
    __syncwarp();

    float h1a_reg[3];
#pragma unroll
    for (int ii = 0; ii < 3; ii++) {
        int i = lane + ii * 32;
        if (i < NAG * NHIDD) {
            int a = i / NHIDD, o = i % NHIDD;
            float acc = bm1a[o];
#pragma unroll
            for (int f = 0; f < NFEAT; f++) acc += s.x[a * NFEAT + f] * Wm1a[o * NFEAT + f];
            h1a_reg[ii] = elu1(acc);
        }
    }
#pragma unroll
    for (int ii = 0; ii < 3; ii++) {
        int i = lane + ii * 32;
        if (i < NAG * NHIDD) s.h1[i] = h1a_reg[ii];
    }
    __syncwarp();
    float h1_reg[3];
#pragma unroll
    for (int ii = 0; ii < 3; ii++) {
        int i = lane + ii * 32;
        if (i < NAG * NHIDD) {
            int a = i / NHIDD, o = i % NHIDD;
            float acc = bm1b[o];
#pragma unroll
            for (int k = 0; k < NHIDD; k++) acc += s.h1[a * NHIDD + k] * Wm1b[o * NHIDD + k];
            h1_reg[ii] = elu1(acc);
        }
    }
    __syncwarp();
#pragma unroll
    for (int ii = 0; ii < 3; ii++) {
        int i = lane + ii * 32;
        if (i < NAG * NHIDD) s.h1[i] = h1_reg[ii];
    }
    __syncwarp();

#pragma unroll
    for (int ii = 0; ii < 5; ii++) {
        int i = lane + ii * 32;
        int part = i / (NAG * NHIDD);
        int rest = i % (NAG * NHIDD);
        int a = rest / NHIDD, o = rest % NHIDD;
        float acc = 0.f;
#pragma unroll
        for (int k = 0; k < NHIDD; k++)
            acc += s.h1[a * NHIDD + k] * Wm2a[o * 16 + part * 8 + k];
        s.p[part][a][o] = acc;
    }
    __syncwarp();

    for (int i = lane; i < E_ * NHIDD; i += 32) {
        int e = i / NHIDD, o = i % NHIDD;
        int r = e / (NAG - 1), jj = e % (NAG - 1);
        int sd = jj < r ? jj : jj + 1;
        s.h2a[i] = elu1(s.p[0][r][o] + s.p[1][sd][o] + bm2a[o]);
    }
    __syncwarp();

    __half* u = g_Uh + (size_t)m * KD;
    for (int i = lane; i < E_ * NHIDD; i += 32) {
        int e = i / NHIDD, o = i % NHIDD;
        float acc = bm2b[o];
#pragma unroll
        for (int k = 0; k < NHIDD; k++) acc += s.h2a[e * NHIDD + k] * Wm2b[o * NHIDD + k];
        u[43 + i] = __float2half(elu1(acc));
    }

    // xemb
    {
        float acc = bx2[lane];
#pragma unroll
        for (int f = 0; f < XDIM - XPERM; f++)
            acc += s.x[XPERM + f] * Wx2[lane * (XDIM - XPERM) + f];
        u[lane] = __float2half(acc);
    }
    if (lane < XSTAT) {
        float acc = bst[lane];
        const float* xdr = xd + (size_t)b * XSTAT;
#pragma unroll
        for (int k = 0; k < XSTAT; k++) acc += xdr[k] * Wst[lane * XSTAT + k];
        u[XEMBD + lane] = __float2half(acc);
    }
    if (lane == 10) u[42] = __float2half(ft[(size_t)b * (T_ + 1) + t]);
    if (lane >= 11 && lane < 16) u[752 + lane] = __float2half(0.f);   // pad 763..767
}

// ------------------------------------------------------------------ repack W -> fp16, n-major; zero out[:,0:2]
__global__ void repack_kernel(const float* __restrict__ Wa1, const float* __restrict__ ba1,
                              const float* __restrict__ Wo1, const float* __restrict__ bo1,
                              const float* __restrict__ Wih, const float* __restrict__ bih,
                              float* __restrict__ out) {
    int idx = blockIdx.x * blockDim.x + threadIdx.x;
    if (idx < ND)
        g_bias[idx] = idx < 128 ? ba1[idx] : (idx < 256 ? bo1[idx - 128] : bih[idx - 256]);

    int stride = gridDim.x * blockDim.x;
    for (int i = idx; i < 2 * M_; i += stride)
        out[(size_t)(i >> 1) * OUTW + (i & 1)] = 0.f;

    for (int i = idx; i < KD * ND; i += stride) {
        int n = i / KD, k = i % KD;
        float v = 0.f;
        if (n < 128) {
            if (k >= 32 && k < 42)       v = Wa1[n * 730 + (k - 32)];
            else if (k >= 43 && k < 763) v = Wa1[n * 730 + 10 + (k - 43)];
        } else if (n < 256) {
            if (k < 763) v = Wo1[(n - 128) * 763 + k];
        } else {
            int r = n - 256;
            if (k < 32)                  v = Wih[r * 753 + k];
            else if (k == 42)            v = Wih[r * 753 + 32];
            else if (k >= 43 && k < 763) v = Wih[r * 753 + 33 + (k - 43)];
        }
        g_Wh[(size_t)n * KD + k] = __float2half(v);
    }
}

// ------------------------------------------------------------------ HMMA GEMM (fp16, K=768), heads fused into epilogue
#define BK      64
#define NCHUNK  (KD / BK)             // 12
#define TILEB   (128 * BK * 2)        // 16 KB
#define STAGEB  (2 * TILEB)           // 32 KB
#define NSTAGE  4
#define SMEMB   (NSTAGE * STAGEB)     // 128 KB

__device__ __forceinline__ void load_chunk(uint32_t stage, int m0, int n0,
                                           int koff, int tid) {
    uint32_t sA = stage, sB = stage + TILEB;
#pragma unroll
    for (int t = 0; t < 2; t++) {
        int i = tid + t * 512;
        int row = i >> 3, cc = i & 7;
        uint32_t off = row * 128 + cc * 16;
        uint32_t sw = off ^ ((off >> 3) & 0x70);
        cpasync16(sA + sw, g_Uh + (size_t)(m0 + row) * KD + koff + cc * 8);
        cpasync16(sB + sw, g_Wh + (size_t)(n0 + row) * KD + koff + cc * 8);
    }
}

__global__ __launch_bounds__(512, 1) void gemm_hmma_kernel(
        const float* __restrict__ Wa2, const float* __restrict__ Wo2,
        float* __restrict__ out) {
    extern __shared__ char smem[];
    uint32_t sb = smem_u32(smem);
    int tid = threadIdx.x;
    int wid = tid >> 5, lane = tid & 31;
    int m0 = blockIdx.y * 128;
    int n0 = blockIdx.x * 128;
    int wm = (wid & 3) * 32;
    int wn = (wid >> 2) * 32;

    int arow = (lane & 7) + ((lane >> 3) & 1) * 8;
    int akc  = (lane >> 4) * 8;
    int l2   = lane & 15;
    int brow = l2 & 7;
    int bkc  = ((l2 >> 3) & 1) * 8;

    float acc[2][4][4];
#pragma unroll
    for (int mt = 0; mt < 2; mt++)
#pragma unroll
        for (int nt = 0; nt < 4; nt++)
#pragma unroll
            for (int r = 0; r < 4; r++) acc[mt][nt][r] = 0.f;

#pragma unroll
    for (int c = 0; c < 3; c++) {
        load_chunk(sb + c * STAGEB, m0, n0, c * BK, tid);
        CP_COMMIT();
    }

    for (int c = 0; c < NCHUNK; c++) {
        if (c + 3 < NCHUNK) CP_WAIT(2); else CP_WAIT(0);
        __syncthreads();
        if (c + 3 < NCHUNK) {
            load_chunk(sb + ((c + 3) & 3) * STAGEB, m0, n0, (c + 3) * BK, tid);
            CP_COMMIT();
        }

        uint32_t sA = sb + (c & 3) * STAGEB;
        uint32_t sB = sA + TILEB;
#pragma unroll
        for (int ks = 0; ks < 4; ks++) {
            uint32_t a[2][4];
#pragma unroll
            for (int mt = 0; mt < 2; mt++) {
                uint32_t off = (uint32_t)(wm + mt * 16 + arow) * 128 + (ks * 16 + akc) * 2;
                off ^= (off >> 3) & 0x70;
                ldsm_x4(a[mt][0], a[mt][1], a[mt][2], a[mt][3], sA + off);
            }
#pragma unroll
            for (int nt = 0; nt < 4; nt++) {
                uint32_t off = (uint32_t)(wn + nt * 8 + brow) * 128 + (ks * 16 + bkc) * 2;
                off ^= (off >> 3) & 0x70;
                uint32_t b0, b1;
                ldsm_x2(b0, b1, sB + off);
#pragma unroll
                for (int mt = 0; mt < 2; mt++)
                    mma16816(acc[mt][nt], a[mt][0], a[mt][1], a[mt][2], a[mt][3], b0, b1);
            }
        }
    }

    int tq = lane >> 2, tr = lane & 3;

    if (blockIdx.x >= 2) {
        int cb = n0 - 256;
#pragma unroll
        for (int nt = 0; nt < 4; nt++) {
            int col = wn + nt * 8 + tr * 2;
            float2 bv = *(const float2*)&g_bias[n0 + col];
#pragma unroll
            for (int mt = 0; mt < 2; mt++) {
                size_t row0 = (size_t)m0 + wm + mt * 16 + tq;
                float2 v0 = {acc[mt][nt][0] + bv.x, acc[mt][nt][1] + bv.y};
                float2 v1 = {acc[mt][nt][2] + bv.x, acc[mt][nt][3] + bv.y};
                *(float2*)(g_C + row0 * GID + cb + col) = v0;
                *(float2*)(g_C + (row0 + 8) * GID + cb + col) = v1;
            }
        }
    } else {
        const float* w2 = blockIdx.x == 0 ? Wa2 : Wo2;
        int hid = blockIdx.x;
        float part[2][2] = {{0.f, 0.f}, {0.f, 0.f}};
#pragma unroll
        for (int nt = 0; nt < 4; nt++) {
            int col = wn + nt * 8 + tr * 2;
            float2 bv = *(const float2*)&g_bias[n0 + col];
            float w0 = w2[col], w1 = w2[col + 1];
#pragma unroll
            for (int mt = 0; mt < 2; mt++) {
                part[mt][0] += fmaxf(acc[mt][nt][0] + bv.x, 0.f) * w0
                             + fmaxf(acc[mt][nt][1] + bv.y, 0.f) * w1;
                part[mt][1] += fmaxf(acc[mt][nt][2] + bv.x, 0.f) * w0
                             + fmaxf(acc[mt][nt][3] + bv.y, 0.f) * w1;
            }
        }
#pragma unroll
        for (int mt = 0; mt < 2; mt++)
#pragma unroll
            for (int h = 0; h < 2; h++) {
                part[mt][h] += __shfl_xor_sync(0xFFFFFFFFu, part[mt][h], 1);
                part[mt][h] += __shfl_xor_sync(0xFFFFFFFFu, part[mt][h], 2);
            }
        if (tr == 0) {
#pragma unroll
            for (int mt = 0; mt < 2; mt++) {
                size_t row0 = (size_t)m0 + wm + mt * 16 + tq;
                atomicAdd(out + row0 * OUTW + hid, part[mt][0]);
                atomicAdd(out + (row0 + 8) * OUTW + hid, part[mt][1]);
            }
        }
    }
}

// ------------------------------------------------------------------ GRU scan via HMMA: 8 batch rows / block, 32 blocks
// gh[384x8] = W_hh[384x128] (static fp16 fragments in regs) x h[128x8] (fp16 built per step)
#define GBATCH 8
#define HPITCH 132
#define GIPITCH 392

__global__ __launch_bounds__(384, 1) void gru_mma_kernel(
        const float* __restrict__ Whh, const float* __restrict__ bhh,
        const float* __restrict__ h0,  float* __restrict__ out) {
    __shared__ __align__(16) float s_h[GBATCH][HPITCH];      // fp32 hidden
    __shared__ __align__(16) float s_gh[3 * HIDD][GBATCH];   // W_hh*h per step
    __shared__ __align__(16) float s_gi[2][GBATCH][GIPITCH]; // gi double buffer
    __shared__ float s_bhh[3 * HIDD];

    int tid = threadIdx.x;
    int wid = tid >> 5, lane = tid & 31;
    int tq = lane >> 2, tr = lane & 3;
    int b0g = blockIdx.x * GBATCH;
    int wm = wid * 32;

    // static A fragments: W_hh rows [wm..wm+31], all K
    uint32_t afr[2][8][4];
#pragma unroll
    for (int mt = 0; mt < 2; mt++)
#pragma unroll
        for (int kt = 0; kt < 8; kt++) {
            int r0 = wm + mt * 16 + tq;
            int k0 = kt * 16 + tr * 2;
            const float* w0 = Whh + (size_t)r0 * HIDD + k0;
            const float* w1 = Whh + (size_t)(r0 + 8) * HIDD + k0;
            afr[mt][kt][0] = f2h2(w0[0], w0[1]);
            afr[mt][kt][1] = f2h2(w1[0], w1[1]);
            afr[mt][kt][2] = f2h2(w0[8], w0[9]);
            afr[mt][kt][3] = f2h2(w1[8], w1[9]);
        }
    s_bhh[tid] = bhh[tid];

    for (int i = tid; i < GBATCH * HIDD; i += 384) {
        int b = i >> 7, j = i & 127;
        s_h[b][j] = h0[(size_t)(b0g + b) * HIDD + j];
    }
    // gi for t=0
    for (int v = tid; v < GBATCH * 96; v += 384) {
        int b = v / 96, c4 = (v % 96) * 4;
        *(float4*)&s_gi[0][b][c4] =
            *(const float4*)(g_C + ((size_t)(b0g + b) * T_) * GID + c4);
    }
    __syncthreads();

    for (int t = 0; t < T_; t++) {
        // prefetch gi(t+1) into regs
        float4 pf0, pf1;
        if (t + 1 < T_) {
            int v0 = tid, v1 = tid + 384;
            int b0i = v0 / 96, c40 = (v0 % 96) * 4;
            int b1i = v1 / 96, c41 = (v1 % 96) * 4;
            pf0 = *(const float4*)(g_C + ((size_t)(b0g + b0i) * T_ + t + 1) * GID + c40);
            pf1 = *(const float4*)(g_C + ((size_t)(b0g + b1i) * T_ + t + 1) * GID + c41);
        }

        // B fragments from s_h + MMA
        float d0[4] = {0.f, 0.f, 0.f, 0.f};
        float d1[4] = {0.f, 0.f, 0.f, 0.f};
#pragma unroll
        for (int kt = 0; kt < 8; kt++) {
            int k0 = kt * 16 + tr * 2;
            uint32_t bf0 = f2h2(s_h[tq][k0],     s_h[tq][k0 + 1]);
            uint32_t bf1 = f2h2(s_h[tq][k0 + 8], s_h[tq][k0 + 9]);
            mma16816(d0, afr[0][kt][0], afr[0][kt][1], afr[0][kt][2], afr[0][kt][3], bf0, bf1);
            mma16816(d1, afr[1][kt][0], afr[1][kt][1], afr[1][kt][2], afr[1][kt][3], bf0, bf1);
        }
        // write gh: rows (wm+mt*16+tq, +8), cols (2tr, 2tr+1)
        {
            int r0 = wm + tq;
            *(float2*)&s_gh[r0][tr * 2]      = make_float2(d0[0], d0[1]);
            *(float2*)&s_gh[r0 + 8][tr * 2]  = make_float2(d0[2], d0[3]);
            *(float2*)&s_gh[r0 + 16][tr * 2] = make_float2(d1[0], d1[1]);
            *(float2*)&s_gh[r0 + 24][tr * 2] = make_float2(d1[2], d1[3]);
        }
        __syncthreads();

        // gate update: 1024 (j,b) pairs
        const float* gib = &s_gi[t & 1][0][0];
        for (int idx = tid; idx < GBATCH * HIDD; idx += 384) {
            int j = idx >> 3, b = idx & 7;
            const float* gir = gib + b * GIPITCH;
            float gr = gir[j]           + s_gh[j][b]          + s_bhh[j];
            float gz = gir[HIDD + j]    + s_gh[HIDD + j][b]   + s_bhh[HIDD + j];
            float hn = s_gh[2 * HIDD + j][b] + s_bhh[2 * HIDD + j];
            float gn = gir[2 * HIDD + j];
            float r = sig_fast(gr);
            float z = sig_fast(gz);
            float n = tanh_fast(gn + r * hn);
            float hv = (1.f - z) * n + z * s_h[b][j];
            s_h[b][j] = hv;
            out[((size_t)(b0g + b) * T_ + t) * OUTW + 2 + j] = hv;
        }
        // store prefetched gi
        if (t + 1 < T_) {
            int v0 = tid, v1 = tid + 384;
            *(float4*)&s_gi[(t + 1) & 1][v0 / 96][(v0 % 96) * 4] = pf0;
            *(float4*)&s_gi[(t + 1) & 1][v1 / 96][(v1 % 96) * 4] = pf1;
        }
        __syncthreads();
    }
}

// ------------------------------------------------------------------
extern "C" void kernel_launch(void* const* d_in, const int* in_sizes, int n_in,
                              void* d_out, int out_size) {
    const float* x     = (const float*)d_in[0];
    const float* xdemo = (const float*)d_in[1];
    const float* ft    = (const float*)d_in[2];
    const float* h0    = (const float*)d_in[3];
    const float* Wx2   = (const float*)d_in[4];
    const float* bx2   = (const float*)d_in[5];
    const float* Wst   = (const float*)d_in[6];
    const float* bst   = (const float*)d_in[7];
    const float* Wm1a  = (const float*)d_in[8];
    const float* bm1a  = (const float*)d_in[9];
    const float* Wm1b  = (const float*)d_in[10];
    const float* bm1b  = (const float*)d_in[11];
    const float* Wm2a  = (const float*)d_in[12];
    const float* bm2a  = (const float*)d_in[13];
    const float* Wm2b  = (const float*)d_in[14];
    const float* bm2b  = (const float*)d_in[15];
    const float* Wa1   = (const float*)d_in[16];
    const float* ba1   = (const float*)d_in[17];
    const float* Wa2   = (const float*)d_in[18];
    const float* Wo1   = (const float*)d_in[19];
    const float* bo1   = (const float*)d_in[20];
    const float* Wo2   = (const float*)d_in[21];
    const float* Wih   = (const float*)d_in[22];
    const float* bih   = (const float*)d_in[23];
    const float* Whh   = (const float*)d_in[24];
    const float* bhh   = (const float*)d_in[25];
    float* out = (float*)d_out;

    cudaFuncSetAttribute(gemm_hmma_kernel,
                         cudaFuncAttributeMaxDynamicSharedMemorySize, SMEMB);

    repack_kernel<<<480, 256>>>(Wa1, ba1, Wo1, bo1, Wih, bih, out);
    feat_kernel<<<M_ / FWARPS, FWARPS * 32>>>(x, ft, xdemo, Wst, bst,
                                              Wm1a, bm1a, Wm1b, bm1b,
                                              Wm2a, bm2a, Wm2b, bm2b, Wx2, bx2);
    gemm_hmma_kernel<<<dim3(ND / 128, M_ / 128), 512, SMEMB>>>(Wa2, Wo2, out);
    gru_mma_kernel<<<B_ / GBATCH, 384>>>(Whh, bhh, h0, out);
}

// round 9
// speedup vs baseline: 3.8606x; 1.1294x over previous
#include <cuda_runtime.h>
#include <cuda_fp16.h>
#include <math.h>
#include <stdint.h>

#define B_    256
#define T_    64
#define NAG   10
#define NFEAT 4
#define XDIM  44
#define XPERM 40
#define XSTAT 10
#define HIDD  128
#define XEMBD 32
#define NHIDD 8
#define E_    90
#define M_    (B_ * T_)      // 16384
#define KD    768            // padded from 763
#define ND    640            // logical: 128 (a) + 128 (o) + 384 (gi)
#define GID   384            // stored C width (gi only)
#define OUTW  130

// ---- scratch ----
__device__ __align__(16) __half g_Uh[(size_t)M_ * KD];    // 24 MB
__device__ __align__(16) __half g_Wh[(size_t)ND * KD];    // 0.94 MB (n-major)
__device__ __align__(16) float g_bias[ND];
__device__ __align__(16) float g_C[(size_t)M_ * GID];     // 25 MB (gi only)

// ------------------------------------------------------------------ PTX helpers
__device__ __forceinline__ uint32_t smem_u32(const void* p) {
    uint32_t a;
    asm("{ .reg .u64 t; cvta.to.shared.u64 t, %1; cvt.u32.u64 %0, t; }" : "=r"(a) : "l"(p));
    return a;
}
__device__ __forceinline__ void cpasync16(uint32_t dst, const void* src) {
    asm volatile("cp.async.cg.shared.global [%0], [%1], 16;" :: "r"(dst), "l"(src) : "memory");
}
#define CP_COMMIT() asm volatile("cp.async.commit_group;" ::: "memory")
#define CP_WAIT(n)  asm volatile("cp.async.wait_group %0;" :: "n"(n) : "memory")

__device__ __forceinline__ void ldsm_x4(uint32_t& r0, uint32_t& r1, uint32_t& r2, uint32_t& r3,
                                        uint32_t addr) {
    asm volatile("ldmatrix.sync.aligned.m8n8.x4.shared.b16 {%0,%1,%2,%3}, [%4];"
                 : "=r"(r0), "=r"(r1), "=r"(r2), "=r"(r3) : "r"(addr));
}
__device__ __forceinline__ void ldsm_x2(uint32_t& r0, uint32_t& r1, uint32_t addr) {
    asm volatile("ldmatrix.sync.aligned.m8n8.x2.shared.b16 {%0,%1}, [%2];"
                 : "=r"(r0), "=r"(r1) : "r"(addr));
}
__device__ __forceinline__ void mma16816(float* d, uint32_t a0, uint32_t a1, uint32_t a2,
                                         uint32_t a3, uint32_t b0, uint32_t b1) {
    asm volatile("mma.sync.aligned.m16n8k16.row.col.f32.f16.f16.f32 "
                 "{%0,%1,%2,%3}, {%4,%5,%6,%7}, {%8,%9}, {%0,%1,%2,%3};"
                 : "+f"(d[0]), "+f"(d[1]), "+f"(d[2]), "+f"(d[3])
                 : "r"(a0), "r"(a1), "r"(a2), "r"(a3), "r"(b0), "r"(b1));
}
__device__ __forceinline__ float tanh_fast(float x) {
    float y;
    asm("tanh.approx.f32 %0, %1;" : "=f"(y) : "f"(x));
    return y;
}
__device__ __forceinline__ float sig_fast(float x) {
    return 0.5f + 0.5f * tanh_fast(0.5f * x);
}
__device__ __forceinline__ uint32_t f2h2(float lo, float hi) {
    uint32_t r;
    asm("cvt.rn.f16x2.f32 %0, %2, %1;" : "=r"(r) : "f"(lo), "f"(hi));
    return r;
}

// ------------------------------------------------------------------ feat: one WARP per (b,t); demo fused in
__device__ __forceinline__ float elu1(float v) { return v > 0.f ? v : __expf(v) - 1.f; }

#define FWARPS 8

struct FeatScratch {
    float x[XDIM];
    float h1[NAG * NHIDD];
    float p[2][NAG][NHIDD];
    float h2a[E_ * NHIDD];
};

__global__ __launch_bounds__(FWARPS * 32) void feat_kernel(
        const float* __restrict__ x,
        const float* __restrict__ ft,
        const float* __restrict__ xd,   const float* __restrict__ Wst,
        const float* __restrict__ bst,
        const float* __restrict__ Wm1a, const float* __restrict__ bm1a,
        const float* __restrict__ Wm1b, const float* __restrict__ bm1b,
        const float* __restrict__ Wm2a, const float* __restrict__ bm2a,
        const float* __restrict__ Wm2b, const float* __restrict__ bm2b,
        const float* __restrict__ Wx2,  const float* __restrict__ bx2) {
    __shared__ FeatScratch sc[FWARPS];
    int w = threadIdx.x >> 5;
    int lane = threadIdx.x & 31;
    int m = blockIdx.x * FWARPS + w;
    int b = m / T_, t = m % T_;
    FeatScratch& s = sc[w];

    const float* xr = x + ((size_t)b * (T_ + 1) + t) * XDIM;
    s.x[lane] = xr[lane];
    if (lane < XDIM - 32) s.x[32 + lane] = xr[32 + lane];
    __syncwarp();

    float h1a_reg[3];
#pragma unroll
    for (int ii = 0; ii < 3; ii++) {
        int i = lane + ii * 32;
        if (i < NAG * NHIDD) {
            int a = i / NHIDD, o = i % NHIDD;
            float acc = bm1a[o];
#pragma unroll
            for (int f = 0; f < NFEAT; f++) acc += s.x[a * NFEAT + f] * Wm1a[o * NFEAT + f];
            h1a_reg[ii] = elu1(acc);
        }
    }
#pragma unroll
    for (int ii = 0; ii < 3; ii++) {
        int i = lane + ii * 32;
        if (i < NAG * NHIDD) s.h1[i] = h1a_reg[ii];
    }
    __syncwarp();
    float h1_reg[3];
#pragma unroll
    for (int ii = 0; ii < 3; ii++) {
        int i = lane + ii * 32;
        if (i < NAG * NHIDD) {
            int a = i / NHIDD, o = i % NHIDD;
            float acc = bm1b[o];
#pragma unroll
            for (int k = 0; k < NHIDD; k++) acc += s.h1[a * NHIDD + k] * Wm1b[o * NHIDD + k];
            h1_reg[ii] = elu1(acc);
        }
    }
    __syncwarp();
#pragma unroll
    for (int ii = 0; ii < 3; ii++) {
        int i = lane + ii * 32;
        if (i < NAG * NHIDD) s.h1[i] = h1_reg[ii];
    }
    __syncwarp();

#pragma unroll
    for (int ii = 0; ii < 5; ii++) {
        int i = lane + ii * 32;
        int part = i / (NAG * NHIDD);
        int rest = i % (NAG * NHIDD);
        int a = rest / NHIDD, o = rest % NHIDD;
        float acc = 0.f;
#pragma unroll
        for (int k = 0; k < NHIDD; k++)
            acc += s.h1[a * NHIDD + k] * Wm2a[o * 16 + part * 8 + k];
        s.p[part][a][o] = acc;
    }
    __syncwarp();

    for (int i = lane; i < E_ * NHIDD; i += 32) {
        int e = i / NHIDD, o = i % NHIDD;
        int r = e / (NAG - 1), jj = e % (NAG - 1);
        int sd = jj < r ? jj : jj + 1;
        s.h2a[i] = elu1(s.p[0][r][o] + s.p[1][sd][o] + bm2a[o]);
    }
    __syncwarp();

    __half* u = g_Uh + (size_t)m * KD;
    for (int i = lane; i < E_ * NHIDD; i += 32) {
        int e = i / NHIDD, o = i % NHIDD;
        float acc = bm2b[o];
#pragma unroll
        for (int k = 0; k < NHIDD; k++) acc += s.h2a[e * NHIDD + k] * Wm2b[o * NHIDD + k];
        u[43 + i] = __float2half(elu1(acc));
    }

    {
        float acc = bx2[lane];
#pragma unroll
        for (int f = 0; f < XDIM - XPERM; f++)
            acc += s.x[XPERM + f] * Wx2[lane * (XDIM - XPERM) + f];
        u[lane] = __float2half(acc);
    }
    if (lane < XSTAT) {
        float acc = bst[lane];
        const float* xdr = xd + (size_t)b * XSTAT;
#pragma unroll
        for (int k = 0; k < XSTAT; k++) acc += xdr[k] * Wst[lane * XSTAT + k];
        u[XEMBD + lane] = __float2half(acc);
    }
    if (lane == 10) u[42] = __float2half(ft[(size_t)b * (T_ + 1) + t]);
    if (lane >= 11 && lane < 16) u[752 + lane] = __float2half(0.f);   // pad 763..767
}

// ------------------------------------------------------------------ repack W -> fp16, n-major; zero out[:,0:2]
__global__ void repack_kernel(const float* __restrict__ Wa1, const float* __restrict__ ba1,
                              const float* __restrict__ Wo1, const float* __restrict__ bo1,
                              const float* __restrict__ Wih, const float* __restrict__ bih,
                              float* __restrict__ out) {
    int idx = blockIdx.x * blockDim.x + threadIdx.x;
    if (idx < ND)
        g_bias[idx] = idx < 128 ? ba1[idx] : (idx < 256 ? bo1[idx - 128] : bih[idx - 256]);

    int stride = gridDim.x * blockDim.x;
    for (int i = idx; i < 2 * M_; i += stride)
        out[(size_t)(i >> 1) * OUTW + (i & 1)] = 0.f;

    for (int i = idx; i < KD * ND; i += stride) {
        int n = i / KD, k = i % KD;
        float v = 0.f;
        if (n < 128) {
            if (k >= 32 && k < 42)       v = Wa1[n * 730 + (k - 32)];
            else if (k >= 43 && k < 763) v = Wa1[n * 730 + 10 + (k - 43)];
        } else if (n < 256) {
            if (k < 763) v = Wo1[(n - 128) * 763 + k];
        } else {
            int r = n - 256;
            if (k < 32)                  v = Wih[r * 753 + k];
            else if (k == 42)            v = Wih[r * 753 + 32];
            else if (k >= 43 && k < 763) v = Wih[r * 753 + 33 + (k - 43)];
        }
        g_Wh[(size_t)n * KD + k] = __float2half(v);
    }
}

// ------------------------------------------------------------------ HMMA GEMM (fp16, K=768), heads fused into epilogue
#define BK      64
#define NCHUNK  (KD / BK)             // 12
#define TILEB   (128 * BK * 2)        // 16 KB
#define STAGEB  (2 * TILEB)           // 32 KB
#define NSTAGE  4
#define SMEMB   (NSTAGE * STAGEB)     // 128 KB

__device__ __forceinline__ void load_chunk(uint32_t stage, int m0, int n0,
                                           int koff, int tid) {
    uint32_t sA = stage, sB = stage + TILEB;
#pragma unroll
    for (int t = 0; t < 2; t++) {
        int i = tid + t * 512;
        int row = i >> 3, cc = i & 7;
        uint32_t off = row * 128 + cc * 16;
        uint32_t sw = off ^ ((off >> 3) & 0x70);
        cpasync16(sA + sw, g_Uh + (size_t)(m0 + row) * KD + koff + cc * 8);
        cpasync16(sB + sw, g_Wh + (size_t)(n0 + row) * KD + koff + cc * 8);
    }
}

__global__ __launch_bounds__(512, 1) void gemm_hmma_kernel(
        const float* __restrict__ Wa2, const float* __restrict__ Wo2,
        float* __restrict__ out) {
    extern __shared__ char smem[];
    uint32_t sb = smem_u32(smem);
    int tid = threadIdx.x;
    int wid = tid >> 5, lane = tid & 31;
    int m0 = blockIdx.y * 128;
    int n0 = blockIdx.x * 128;
    int wm = (wid & 3) * 32;
    int wn = (wid >> 2) * 32;

    int arow = (lane & 7) + ((lane >> 3) & 1) * 8;
    int akc  = (lane >> 4) * 8;
    int l2   = lane & 15;
    int brow = l2 & 7;
    int bkc  = ((l2 >> 3) & 1) * 8;

    float acc[2][4][4];
#pragma unroll
    for (int mt = 0; mt < 2; mt++)
#pragma unroll
        for (int nt = 0; nt < 4; nt++)
#pragma unroll
            for (int r = 0; r < 4; r++) acc[mt][nt][r] = 0.f;

#pragma unroll
    for (int c = 0; c < 3; c++) {
        load_chunk(sb + c * STAGEB, m0, n0, c * BK, tid);
        CP_COMMIT();
    }

    for (int c = 0; c < NCHUNK; c++) {
        if (c + 3 < NCHUNK) CP_WAIT(2); else CP_WAIT(0);
        __syncthreads();
        if (c + 3 < NCHUNK) {
            load_chunk(sb + ((c + 3) & 3) * STAGEB, m0, n0, (c + 3) * BK, tid);
            CP_COMMIT();
        }

        uint32_t sA = sb + (c & 3) * STAGEB;
        uint32_t sB = sA + TILEB;
#pragma unroll
        for (int ks = 0; ks < 4; ks++) {
            uint32_t a[2][4];
#pragma unroll
            for (int mt = 0; mt < 2; mt++) {
                uint32_t off = (uint32_t)(wm + mt * 16 + arow) * 128 + (ks * 16 + akc) * 2;
                off ^= (off >> 3) & 0x70;
                ldsm_x4(a[mt][0], a[mt][1], a[mt][2], a[mt][3], sA + off);
            }
#pragma unroll
            for (int nt = 0; nt < 4; nt++) {
                uint32_t off = (uint32_t)(wn + nt * 8 + brow) * 128 + (ks * 16 + bkc) * 2;
                off ^= (off >> 3) & 0x70;
                uint32_t b0, b1;
                ldsm_x2(b0, b1, sB + off);
#pragma unroll
                for (int mt = 0; mt < 2; mt++)
                    mma16816(acc[mt][nt], a[mt][0], a[mt][1], a[mt][2], a[mt][3], b0, b1);
            }
        }
    }

    int tq = lane >> 2, tr = lane & 3;

    if (blockIdx.x >= 2) {
        int cb = n0 - 256;
#pragma unroll
        for (int nt = 0; nt < 4; nt++) {
            int col = wn + nt * 8 + tr * 2;
            float2 bv = *(const float2*)&g_bias[n0 + col];
#pragma unroll
            for (int mt = 0; mt < 2; mt++) {
                size_t row0 = (size_t)m0 + wm + mt * 16 + tq;
                float2 v0 = {acc[mt][nt][0] + bv.x, acc[mt][nt][1] + bv.y};
                float2 v1 = {acc[mt][nt][2] + bv.x, acc[mt][nt][3] + bv.y};
                *(float2*)(g_C + row0 * GID + cb + col) = v0;
                *(float2*)(g_C + (row0 + 8) * GID + cb + col) = v1;
            }
        }
    } else {
        const float* w2 = blockIdx.x == 0 ? Wa2 : Wo2;
        int hid = blockIdx.x;
        float part[2][2] = {{0.f, 0.f}, {0.f, 0.f}};
#pragma unroll
        for (int nt = 0; nt < 4; nt++) {
            int col = wn + nt * 8 + tr * 2;
            float2 bv = *(const float2*)&g_bias[n0 + col];
            float w0 = w2[col], w1 = w2[col + 1];
#pragma unroll
            for (int mt = 0; mt < 2; mt++) {
                part[mt][0] += fmaxf(acc[mt][nt][0] + bv.x, 0.f) * w0
                             + fmaxf(acc[mt][nt][1] + bv.y, 0.f) * w1;
                part[mt][1] += fmaxf(acc[mt][nt][2] + bv.x, 0.f) * w0
                             + fmaxf(acc[mt][nt][3] + bv.y, 0.f) * w1;
            }
        }
#pragma unroll
        for (int mt = 0; mt < 2; mt++)
#pragma unroll
            for (int h = 0; h < 2; h++) {
                part[mt][h] += __shfl_xor_sync(0xFFFFFFFFu, part[mt][h], 1);
                part[mt][h] += __shfl_xor_sync(0xFFFFFFFFu, part[mt][h], 2);
            }
        if (tr == 0) {
#pragma unroll
            for (int mt = 0; mt < 2; mt++) {
                size_t row0 = (size_t)m0 + wm + mt * 16 + tq;
                atomicAdd(out + row0 * OUTW + hid, part[mt][0]);
                atomicAdd(out + (row0 + 8) * OUTW + hid, part[mt][1]);
            }
        }
    }
}

// ------------------------------------------------------------------ GRU scan via HMMA, gate-aligned row permutation.
// 8 warps x 3 m-tiles: tile g holds W_hh rows g*128 + [wid*16, wid*16+16).
// After 24 MMAs each thread owns full (r,z,n) triples for its (j, batch)
// pairs -> gates in registers, h in registers, single sync per step.
#define GBATCH 8
#define HPITCH 132

__global__ __launch_bounds__(256, 1) void gru_mma_kernel(
        const float* __restrict__ Whh, const float* __restrict__ bhh,
        const float* __restrict__ h0,  float* __restrict__ out) {
    __shared__ __align__(16) float s_h[2][GBATCH][HPITCH];   // double-buffered hidden

    int tid = threadIdx.x;
    int wid = tid >> 5, lane = tid & 31;
    int tq = lane >> 2, tr = lane & 3;
    int b0g = blockIdx.x * GBATCH;
    int j0 = wid * 16 + tq;            // this thread's hidden indices: j0, j0+8

    // static A fragments: gate g, rows g*128+j0 / +8
    uint32_t afr[3][8][4];
#pragma unroll
    for (int g = 0; g < 3; g++)
#pragma unroll
        for (int kt = 0; kt < 8; kt++) {
            int row0 = g * HIDD + j0;
            int k0 = kt * 16 + tr * 2;
            const float* w0 = Whh + (size_t)row0 * HIDD + k0;
            const float* w1 = Whh + (size_t)(row0 + 8) * HIDD + k0;
            afr[g][kt][0] = f2h2(w0[0], w0[1]);
            afr[g][kt][1] = f2h2(w1[0], w1[1]);
            afr[g][kt][2] = f2h2(w0[8], w0[9]);
            afr[g][kt][3] = f2h2(w1[8], w1[9]);
        }
    float bb[3][2];
#pragma unroll
    for (int g = 0; g < 3; g++) {
        bb[g][0] = bhh[g * HIDD + j0];
        bb[g][1] = bhh[g * HIDD + j0 + 8];
    }

    // h register-resident: hreg[js][bs], j = j0+js*8, b = b0g+2tr+bs
    float hreg[2][2];
    const float* gibase[2];   // g_C row base per bs
    float* outbase[2];
#pragma unroll
    for (int bs = 0; bs < 2; bs++) {
        int b = b0g + 2 * tr + bs;
        hreg[0][bs] = h0[(size_t)b * HIDD + j0];
        hreg[1][bs] = h0[(size_t)b * HIDD + j0 + 8];
        gibase[bs] = g_C + ((size_t)b * T_) * GID + j0;
        outbase[bs] = out + ((size_t)b * T_) * OUTW + 2 + j0;
    }
    for (int i = tid; i < GBATCH * HIDD; i += 256)
        s_h[0][i >> 7][i & 127] = h0[(size_t)(b0g + (i >> 7)) * HIDD + (i & 127)];

    // gi for t=0 (12 scalars)
    float gic[3][4], gin[3][4];
#pragma unroll
    for (int g = 0; g < 3; g++)
#pragma unroll
        for (int js = 0; js < 2; js++)
#pragma unroll
            for (int bs = 0; bs < 2; bs++)
                gic[g][js * 2 + bs] = gibase[bs][g * HIDD + js * 8];
    __syncthreads();

    for (int t = 0; t < T_; t++) {
        // prefetch gi(t+1)
        if (t + 1 < T_) {
#pragma unroll
            for (int g = 0; g < 3; g++)
#pragma unroll
                for (int js = 0; js < 2; js++)
#pragma unroll
                    for (int bs = 0; bs < 2; bs++)
                        gin[g][js * 2 + bs] =
                            gibase[bs][(size_t)(t + 1) * GID + g * HIDD + js * 8];
        }

        int p = t & 1;
        float d[3][4];
#pragma unroll
        for (int g = 0; g < 3; g++)
#pragma unroll
            for (int e = 0; e < 4; e++) d[g][e] = 0.f;

#pragma unroll
        for (int kt = 0; kt < 8; kt++) {
            int k0 = kt * 16 + tr * 2;
            uint32_t bf0 = f2h2(s_h[p][tq][k0],     s_h[p][tq][k0 + 1]);
            uint32_t bf1 = f2h2(s_h[p][tq][k0 + 8], s_h[p][tq][k0 + 9]);
#pragma unroll
            for (int g = 0; g < 3; g++)
                mma16816(d[g], afr[g][kt][0], afr[g][kt][1], afr[g][kt][2], afr[g][kt][3],
                         bf0, bf1);
        }

        // gates fully in registers
#pragma unroll
        for (int js = 0; js < 2; js++)
#pragma unroll
            for (int bs = 0; bs < 2; bs++) {
                int e = js * 2 + bs;
                float r = sig_fast(gic[0][e] + d[0][e] + bb[0][js]);
                float z = sig_fast(gic[1][e] + d[1][e] + bb[1][js]);
                float n = tanh_fast(gic[2][e] + r * (d[2][e] + bb[2][js]));
                float hv = (1.f - z) * n + z * hreg[js][bs];
                hreg[js][bs] = hv;
                s_h[p ^ 1][2 * tr + bs][j0 + js * 8] = hv;
                outbase[bs][(size_t)t * OUTW + js * 8] = hv;
            }

#pragma unroll
        for (int g = 0; g < 3; g++)
#pragma unroll
            for (int e = 0; e < 4; e++) gic[g][e] = gin[g][e];
        __syncthreads();
    }
}

// ------------------------------------------------------------------
extern "C" void kernel_launch(void* const* d_in, const int* in_sizes, int n_in,
                              void* d_out, int out_size) {
    const float* x     = (const float*)d_in[0];
    const float* xdemo = (const float*)d_in[1];
    const float* ft    = (const float*)d_in[2];
    const float* h0    = (const float*)d_in[3];
    const float* Wx2   = (const float*)d_in[4];
    const float* bx2   = (const float*)d_in[5];
    const float* Wst   = (const float*)d_in[6];
    const float* bst   = (const float*)d_in[7];
    const float* Wm1a  = (const float*)d_in[8];
    const float* bm1a  = (const float*)d_in[9];
    const float* Wm1b  = (const float*)d_in[10];
    const float* bm1b  = (const float*)d_in[11];
    const float* Wm2a  = (const float*)d_in[12];
    const float* bm2a  = (const float*)d_in[13];
    const float* Wm2b  = (const float*)d_in[14];
    const float* bm2b  = (const float*)d_in[15];
    const float* Wa1   = (const float*)d_in[16];
    const float* ba1   = (const float*)d_in[17];
    const float* Wa2   = (const float*)d_in[18];
    const float* Wo1   = (const float*)d_in[19];
    const float* bo1   = (const float*)d_in[20];
    const float* Wo2   = (const float*)d_in[21];
    const float* Wih   = (const float*)d_in[22];
    const float* bih   = (const float*)d_in[23];
    const float* Whh   = (const float*)d_in[24];
    const float* bhh   = (const float*)d_in[25];
    float* out = (float*)d_out;

    cudaFuncSetAttribute(gemm_hmma_kernel,
                         cudaFuncAttributeMaxDynamicSharedMemorySize, SMEMB);

    repack_kernel<<<480, 256>>>(Wa1, ba1, Wo1, bo1, Wih, bih, out);
    feat_kernel<<<M_ / FWARPS, FWARPS * 32>>>(x, ft, xdemo, Wst, bst,
                                              Wm1a, bm1a, Wm1b, bm1b,
                                              Wm2a, bm2a, Wm2b, bm2b, Wx2, bx2);
    gemm_hmma_kernel<<<dim3(ND / 128, M_ / 128), 512, SMEMB>>>(Wa2, Wo2, out);
    gru_mma_kernel<<<B_ / GBATCH, 256>>>(Whh, bhh, h0, out);
}